// round 14
// baseline (speedup 1.0000x reference)
#include <cuda_runtime.h>
#include <cuda_bf16.h>
#include <math.h>
#include <stdint.h>

#define B_    2
#define C_    1024
#define N_    80
#define D_    3074
#define KP    3200
#define TD_   9222
#define DFF_  2048
#define OUTD_ 1026
#define M_    160
#define REFINE_ 3

#define KC_D   50
#define KC_F   32
#define CHA    20480    // A chunk bytes (160*128)
#define CHW    8192     // W 64-row tile bytes
// N128 tile counts and padded n64 counts
#define T_IP 73
#define T_OP 25
#define T_L1 16
#define T_L2 25
#define T_OW 9
#define NP_IP 146
#define NP_OP 50
#define NP_L1 32
#define NP_L2 50
#define NP_OW 18

#define S_IP 2
#define S_OP 6
#define S_L1 9
#define S_L2 6
#define S_OW 16
#define PW_Q  9344
#define PW_D  3200
#define PW_L1 2048
#define PW_OW 1152

// ---------------- chunked+swizzled bf16 weights (padded N) ---------------------
__device__ __nv_bfloat16 g_ipw[(size_t)KC_D*NP_IP*4096];
__device__ __nv_bfloat16 g_opw[(size_t)KC_D*NP_OP*4096];
__device__ __nv_bfloat16 g_l1w[(size_t)KC_D*NP_L1*4096];
__device__ __nv_bfloat16 g_l2w[(size_t)KC_F*NP_L2*4096];
__device__ __nv_bfloat16 g_oww[(size_t)KC_D*NP_OW*4096];

// ---------------- chunked+swizzled bf16 activations (GEMM A-side) --------------
__device__ __nv_bfloat16 g_tokc[(size_t)KC_D*10240];
__device__ __nv_bfloat16 g_avc [(size_t)KC_D*10240];
__device__ __nv_bfloat16 g_xc  [(size_t)KC_D*10240];
__device__ __nv_bfloat16 g_hc  [(size_t)KC_F*10240];
__device__ __nv_bfloat16 g_x2c [(size_t)KC_D*10240];

// ---------------- fp32 activations + split-K partials --------------------------
__device__ float g_preq  [M_*C_];
__device__ float g_firstq[M_*C_];
__device__ float g_curr  [M_*2];
__device__ float g_tokens[M_*KP];
__device__ float g_q     [M_*KP];
__device__ float g_k     [M_*KP];
__device__ float g_v     [M_*KP];
__device__ float g_x     [M_*KP];
__device__ float g_partQ [(size_t)S_IP*M_*PW_Q];
__device__ float g_partD [(size_t)S_OP*M_*PW_D];
__device__ float g_partH [(size_t)S_L1*M_*PW_L1];
__device__ float g_partO [(size_t)S_OW*M_*PW_OW];

// ================= helpers =======================================================
__device__ __forceinline__ uint32_t smem_u32(const void* p) {
    uint32_t a;
    asm("{ .reg .u64 t; cvta.to.shared.u64 t, %1; cvt.u32.u64 %0, t; }" : "=r"(a) : "l"(p));
    return a;
}

#define SW128(bo) ((bo) ^ (((bo) >> 3) & 0x70))

__device__ __forceinline__ void mbar_init(uint32_t mbar, uint32_t cnt) {
    asm volatile("mbarrier.init.shared.b64 [%0], %1;" :: "r"(mbar), "r"(cnt) : "memory");
}
__device__ __forceinline__ void mbar_expect(uint32_t mbar, uint32_t bytes) {
    asm volatile("mbarrier.arrive.expect_tx.shared.b64 _, [%0], %1;"
                 :: "r"(mbar), "r"(bytes) : "memory");
}
__device__ __forceinline__ void mbar_wait(uint32_t mbar, uint32_t parity) {
    asm volatile(
        "{\n\t"
        ".reg .pred P1;\n\t"
        "LAB_%=:\n\t"
        "mbarrier.try_wait.parity.acquire.cta.shared::cta.b64 P1, [%0], %1, 0x989680;\n\t"
        "@P1 bra.uni DONE_%=;\n\t"
        "bra.uni LAB_%=;\n\t"
        "DONE_%=:\n\t"
        "}"
        :: "r"(mbar), "r"(parity) : "memory");
}
__device__ __forceinline__ void fence_async() {
    asm volatile("fence.proxy.async.shared::cta;" ::: "memory");
}
__device__ __forceinline__ void bulk_ld(uint32_t dst, const void* src, uint32_t bytes, uint32_t bar) {
    asm volatile(
        "cp.async.bulk.shared::cluster.global.mbarrier::complete_tx::bytes [%0], [%1], %2, [%3];"
        :: "r"(dst), "l"(src), "r"(bytes), "r"(bar) : "memory");
}
__device__ __forceinline__ void ldsm4(uint32_t* r, uint32_t addr) {
    asm volatile("ldmatrix.sync.aligned.m8n8.x4.shared.b16 {%0,%1,%2,%3}, [%4];"
                 : "=r"(r[0]), "=r"(r[1]), "=r"(r[2]), "=r"(r[3]) : "r"(addr));
}
__device__ __forceinline__ void mma16816(float c[4], const uint32_t a[4],
                                         uint32_t b0, uint32_t b1) {
    asm volatile(
        "mma.sync.aligned.m16n8k16.row.col.f32.bf16.bf16.f32 "
        "{%0,%1,%2,%3},{%4,%5,%6,%7},{%8,%9},{%0,%1,%2,%3};"
        : "+f"(c[0]), "+f"(c[1]), "+f"(c[2]), "+f"(c[3])
        : "r"(a[0]), "r"(a[1]), "r"(a[2]), "r"(a[3]), "r"(b0), "r"(b1));
}

// ================= bilinear sampling ============================================
struct Bil { int i0,i1,j0,j1; float w00,w01,w10,w11; };

__device__ __forceinline__ Bil make_bil(int py, int px) {
    float cy = ((float)py + 0.5f) * (14.0f/224.0f) - 0.5f;
    float cx = ((float)px + 0.5f) * (14.0f/224.0f) - 0.5f;
    float fy = floorf(cy), fx = floorf(cx);
    float ay = cy - fy,    ax = cx - fx;
    int y0 = (int)fy, x0 = (int)fx;
    Bil b;
    b.i0 = min(13, max(0, y0));   b.i1 = min(13, max(0, y0+1));
    b.j0 = min(13, max(0, x0));   b.j1 = min(13, max(0, x0+1));
    b.w00 = (1.f-ay)*(1.f-ax); b.w01 = (1.f-ay)*ax;
    b.w10 = ay*(1.f-ax);       b.w11 = ay*ax;
    return b;
}

__device__ __forceinline__ float bil_sample(const float* __restrict__ f, int c, const Bil& b) {
    const float* p = f + c*196;
    return b.w00*p[b.i0*14 + b.j0] + b.w01*p[b.i0*14 + b.j1]
         + b.w10*p[b.i1*14 + b.j0] + b.w11*p[b.i1*14 + b.j1];
}

__device__ __forceinline__ uint4 pack8(const float* v) {
    uint4 r;
    __nv_bfloat162 b0 = __float22bfloat162_rn(make_float2(v[0], v[1]));
    __nv_bfloat162 b1 = __float22bfloat162_rn(make_float2(v[2], v[3]));
    __nv_bfloat162 b2 = __float22bfloat162_rn(make_float2(v[4], v[5]));
    __nv_bfloat162 b3 = __float22bfloat162_rn(make_float2(v[6], v[7]));
    r.x = *(uint32_t*)&b0; r.y = *(uint32_t*)&b1;
    r.z = *(uint32_t*)&b2; r.w = *(uint32_t*)&b3;
    return r;
}

// ================= weight conversion (padded N, zero-filled) ====================
__global__ void k_wconv(const float* __restrict__ ipw, const float* __restrict__ opw,
                        const float* __restrict__ l1w, const float* __restrict__ l2w,
                        const float* __restrict__ oww) {
    int b = blockIdx.x;
    const float* src; __nv_bfloat16* dst;
    int N, K, KC, NP, n;
    if (b < 9344)       { n = b;         src = ipw; dst = g_ipw; N = TD_;  K = D_;   KC = KC_D; NP = NP_IP; }
    else if (b < 12544) { n = b - 9344;  src = opw; dst = g_opw; N = D_;   K = D_;   KC = KC_D; NP = NP_OP; }
    else if (b < 14592) { n = b - 12544; src = l1w; dst = g_l1w; N = DFF_; K = D_;   KC = KC_D; NP = NP_L1; }
    else if (b < 17792) { n = b - 14592; src = l2w; dst = g_l2w; N = D_;   K = DFF_; KC = KC_F; NP = NP_L2; }
    else                { n = b - 17792; src = oww; dst = g_oww; N = OUTD_;K = D_;   KC = KC_D; NP = NP_OW; }

    bool nok = n < N;
    const float* srow = src + (size_t)n * K;
    char* dbase = (char*)dst + (size_t)(n >> 6) * CHW;
    uint32_t lrow = (uint32_t)((n & 63) * 128);
    size_t kstride = (size_t)NP * CHW;
    int units = KC * 8;

    for (int u = threadIdx.x; u < units; u += 128) {
        int k0 = u * 8;
        float v[8];
        if (nok && k0 + 8 <= K) {
            float2 f0 = *(const float2*)(srow + k0);
            float2 f1 = *(const float2*)(srow + k0 + 2);
            float2 f2 = *(const float2*)(srow + k0 + 4);
            float2 f3 = *(const float2*)(srow + k0 + 6);
            v[0]=f0.x; v[1]=f0.y; v[2]=f1.x; v[3]=f1.y;
            v[4]=f2.x; v[5]=f2.y; v[6]=f3.x; v[7]=f3.y;
        } else {
            #pragma unroll
            for (int e = 0; e < 8; e++)
                v[e] = (nok && (k0 + e) < K) ? srow[k0 + e] : 0.f;
        }
        uint32_t loc = lrow + (uint32_t)((k0 & 63) * 2);
        *(uint4*)(dbase + (size_t)(k0 >> 6) * kstride + SW128(loc)) = pack8(v);
    }
}

// ================= gather (align inline) ========================================
__global__ void k_gather(const float* __restrict__ pre_f,
                         const float* __restrict__ first_f,
                         const int* __restrict__ prev,
                         const int* __restrict__ first) {
    int row = blockIdx.x;
    int b = row / N_, j = row % N_;
    __shared__ int sp[N_*2], sf[N_*2];
    __shared__ int skey[256];
    int t = threadIdx.x;
    for (int i = t; i < N_*2; i += 256) {
        sp[i] = prev [b*N_*2 + i];
        sf[i] = first[b*N_*2 + i];
    }
    __syncthreads();
    int key = 0x7FFFFFFF;
    if (t < N_) {
        int acc = 0;
        for (int q = 0; q < N_; q++) {
            int qq = (q - t + N_) % N_;
            acc += abs(sp[q*2]   - sf[qq*2]);
            acc += abs(sp[q*2+1] - sf[qq*2+1]);
        }
        key = acc * 128 + t;
    }
    skey[t] = key; __syncthreads();
    for (int s = 128; s >= 1; s >>= 1) {
        if (t < s) skey[t] = min(skey[t], skey[t+s]);
        __syncthreads();
    }
    int best = skey[0] & 127;

    int jj = (j - best + N_) % N_;
    int py = sp[j*2], px = sp[j*2+1];
    Bil bp = make_bil(py, px);
    Bil bf = make_bil(sf[jj*2], sf[jj*2+1]);
    const float* pf = pre_f   + b*C_*196;
    const float* ff = first_f + b*C_*196;
    for (int c = t; c < C_; c += 256) {
        g_preq  [row*C_ + c] = bil_sample(pf, c, bp);
        g_firstq[row*C_ + c] = bil_sample(ff, c, bf);
    }
    if (t < KP - D_) {
        g_q[(size_t)row*KP + D_ + t] = 0.f;
        g_k[(size_t)row*KP + D_ + t] = 0.f;
        g_v[(size_t)row*KP + D_ + t] = 0.f;
    }
    if (t == 0) {
        g_curr[row*2]   = (float)py;
        g_curr[row*2+1] = (float)px;
    }
}

// ================= tokens = LN(concat) + pe(inline) =============================
__global__ void k_tokens(const float* __restrict__ curr_f,
                         const float* __restrict__ lng,
                         const float* __restrict__ lnb) {
    int row = blockIdx.x;
    int b = row / N_, n = row % N_;
    __shared__ float srow[D_];
    __shared__ float red[256];
    int t = threadIdx.x;

    float cy = g_curr[row*2], cx = g_curr[row*2+1];
    int py = (int)cy, px = (int)cx;
    Bil bb = make_bil(py, px);
    const float* cf = curr_f + b*C_*196;

    float lsum = 0.f;
    for (int d = t; d < D_; d += 256) {
        float v;
        if      (d < C_)        v = g_preq[row*C_ + d];
        else if (d < 2*C_)      v = bil_sample(cf, d - C_, bb);
        else if (d == 2*C_)     v = cy;
        else if (d == 2*C_+1)   v = cx;
        else                    v = g_firstq[row*C_ + (d - (2*C_+2))];
        srow[d] = v;
        lsum += v;
    }
    red[t] = lsum; __syncthreads();
    for (int s = 128; s >= 1; s >>= 1) { if (t < s) red[t] += red[t+s]; __syncthreads(); }
    float mean = red[0] * (1.f/(float)D_);
    __syncthreads();

    float lsq = 0.f;
    for (int d = t; d < D_; d += 256) { float u = srow[d] - mean; lsq += u*u; }
    red[t] = lsq; __syncthreads();
    for (int s = 128; s >= 1; s >>= 1) { if (t < s) red[t] += red[t+s]; __syncthreads(); }
    float rstd = rsqrtf(red[0] * (1.f/(float)D_) + 1e-5f);
    __syncthreads();

    char* cbase = (char*)g_tokc;
    uint32_t lrow = (uint32_t)(row * 128);
    for (int u = t; u < KP/8; u += 256) {
        int d0 = u * 8;
        float v[8];
        #pragma unroll
        for (int e = 0; e < 8; e++) {
            int d = d0 + e;
            float pe = 0.f;
            if (d < D_) {
                int k2 = d & ~1;
                float div = expf((float)k2 * (-9.210340371976184f / (float)D_));
                float arg = (float)n * div;
                pe = (d & 1) ? cosf(arg) : sinf(arg);
            }
            v[e] = (d < D_) ? (lng[d] * ((srow[d] - mean) * rstd) + lnb[d] + pe) : 0.f;
        }
        float4* fp = (float4*)&g_tokens[(size_t)row*KP + d0];
        fp[0] = make_float4(v[0], v[1], v[2], v[3]);
        fp[1] = make_float4(v[4], v[5], v[6], v[7]);
        uint32_t loc = lrow + (uint32_t)((d0 & 63) * 2);
        *(uint4*)(cbase + (size_t)(d0 >> 6) * CHA + SW128(loc)) = pack8(v);
    }
}

// ================= GEMM: block tile 160x128, warp tile 80x32, split-K ===========
#define NSTG 5
#define STAGE_B (CHA + 2*CHW)                // 36864
#define GEMM_SMEM (NSTG*STAGE_B + 64)        // 184384

__global__ __launch_bounds__(256, 1) void k_gemm(
    const __nv_bfloat16* __restrict__ Ac,
    const __nv_bfloat16* __restrict__ Wc,
    int KC, int NP,
    float* __restrict__ Part, int ldo)
{
    extern __shared__ char sm[];
    uint32_t smb = smem_u32(sm);
    uint32_t mb = smb + NSTG * STAGE_B;

    int t = threadIdx.x;
    int warp = t >> 5, lane = t & 31;
    int wm = (warp >> 2) * 80;
    int wn = (warp & 3) * 32;                 // 0,32,64,96
    int qr = lane >> 2, qc2 = (lane & 3) * 2;
    int nb = blockIdx.x, n0 = nb * 128;
    int z = blockIdx.y, S = gridDim.y;
    int ks0 = (KC * z) / S, ks1 = (KC * (z + 1)) / S;
    int nst = ks1 - ks0;

    int sub   = lane & 7;
    int m_off = ((lane >> 3) & 1) * 8 + sub;
    int k_off = (lane >> 4) * 8;
    uint32_t swz = (uint32_t)(sub * 16);
    uint32_t whalf = (wn >= 64) ? 8192u : 0u;         // which 64-row W tile
    uint32_t wrow0 = (uint32_t)(((wn & 32) + m_off) * 128);
    uint32_t wrow1 = wrow0 + 16 * 128;

    if (t == 0) {
        #pragma unroll
        for (int i = 0; i < NSTG; i++) mbar_init(mb + i*8, 1);
        fence_async();
    }
    __syncthreads();

    float acc[5][4][4];
    #pragma unroll
    for (int i = 0; i < 5; i++)
        #pragma unroll
        for (int j = 0; j < 4; j++)
            #pragma unroll
            for (int r = 0; r < 4; r++) acc[i][j][r] = 0.f;

    if (t == 0) {
        #pragma unroll
        for (int p = 0; p < NSTG - 1; p++) {
            if (p >= nst) break;
            int kg = ks0 + p;
            uint32_t bar = mb + p*8;
            mbar_expect(bar, STAGE_B);
            bulk_ld(smb + p*STAGE_B,       (const char*)Ac + (size_t)kg*CHA, CHA, bar);
            bulk_ld(smb + p*STAGE_B + CHA,
                    (const char*)Wc + ((size_t)kg*NP + nb*2)*CHW, 2*CHW, bar);
        }
    }

    uint32_t amA[5][4], bmA[8], amB[5][4], bmB[8];

    for (int l = 0; l < nst; l++) {
        int s = l % NSTG;
        mbar_wait(mb + s*8, (uint32_t)((l/NSTG) & 1));
        if (t == 0 && l + NSTG - 1 < nst) {
            int kg = ks0 + l + NSTG - 1;
            int s2 = (l + NSTG - 1) % NSTG;
            uint32_t bar = mb + s2*8;
            mbar_expect(bar, STAGE_B);
            bulk_ld(smb + s2*STAGE_B,       (const char*)Ac + (size_t)kg*CHA, CHA, bar);
            bulk_ld(smb + s2*STAGE_B + CHA,
                    (const char*)Wc + ((size_t)kg*NP + nb*2)*CHW, 2*CHW, bar);
        }
        uint32_t as_b = smb + s*STAGE_B;
        uint32_t ws_b = as_b + CHA + whalf;

        #define LDP(BUFam, BUFbm, p) do { \
            uint32_t col_ = ((uint32_t)(((p)*16 + k_off) * 2)) ^ swz; \
            ldsm4(BUFam[0], as_b + (uint32_t)((wm +   0 + m_off) * 128) + col_); \
            ldsm4(BUFam[1], as_b + (uint32_t)((wm +  16 + m_off) * 128) + col_); \
            ldsm4(BUFam[2], as_b + (uint32_t)((wm +  32 + m_off) * 128) + col_); \
            ldsm4(BUFam[3], as_b + (uint32_t)((wm +  48 + m_off) * 128) + col_); \
            ldsm4(BUFam[4], as_b + (uint32_t)((wm +  64 + m_off) * 128) + col_); \
            ldsm4(BUFbm,     ws_b + wrow0 + col_); \
            ldsm4(BUFbm + 4, ws_b + wrow1 + col_); \
        } while (0)

        #define MMAP(BUFam, BUFbm) do { \
            _Pragma("unroll") \
            for (int i_ = 0; i_ < 5; i_++) { \
                mma16816(acc[i_][0], BUFam[i_], BUFbm[0], BUFbm[2]); \
                mma16816(acc[i_][1], BUFam[i_], BUFbm[1], BUFbm[3]); \
                mma16816(acc[i_][2], BUFam[i_], BUFbm[4], BUFbm[6]); \
                mma16816(acc[i_][3], BUFam[i_], BUFbm[5], BUFbm[7]); \
            } \
        } while (0)

        LDP(amA, bmA, 0);
        LDP(amB, bmB, 1);
        MMAP(amA, bmA);
        LDP(amA, bmA, 2);
        MMAP(amB, bmB);
        LDP(amB, bmB, 3);
        MMAP(amA, bmA);
        MMAP(amB, bmB);
        #undef LDP
        #undef MMAP
        __syncthreads();
    }

    // ---- epilogue: fp32 partials ----
    float* dst = Part + (size_t)z * M_ * ldo;
    #pragma unroll
    for (int i = 0; i < 5; i++) {
        #pragma unroll
        for (int j = 0; j < 4; j++) {
            int jn = (j < 2) ? (wn + j*8) : (wn + 16 + (j-2)*8);
            int n = n0 + jn + qc2;
            #pragma unroll
            for (int h = 0; h < 2; h++) {
                int m = wm + i*16 + qr + h*8;
                dst[(size_t)m * ldo + n]     = acc[i][j][h*2 + 0];
                dst[(size_t)m * ldo + n + 1] = acc[i][j][h*2 + 1];
            }
        }
    }
}

// ================= qkv reduction: q/k/v = Σ partials + bias =====================
__global__ void k_qkvred(const float* __restrict__ bias) {
    int row = blockIdx.x;
    int t = threadIdx.x;
    const float* p0 = &g_partQ[(size_t)row * PW_Q];
    const float* p1 = &g_partQ[((size_t)M_ + row) * PW_Q];
    for (int n = t * 2; n < TD_; n += 512) {
        float2 a = *(const float2*)(p0 + n);
        float2 b = *(const float2*)(p1 + n);
        float2 bb = *(const float2*)(bias + n);
        float v0 = a.x + b.x + bb.x;
        float v1 = a.y + b.y + bb.y;
        int seg0 = (n >= 6148) ? 2 : (n >= 3074 ? 1 : 0);
        float* dst0 = (seg0 == 0) ? g_q : (seg0 == 1 ? g_k : g_v);
        dst0[(size_t)row * KP + (n - seg0 * 3074)] = v0;
        int n1 = n + 1;
        if (n1 < TD_) {
            int seg1 = (n1 >= 6148) ? 2 : (n1 >= 3074 ? 1 : 0);
            float* dst1 = (seg1 == 0) ? g_q : (seg1 == 1 ? g_k : g_v);
            dst1[(size_t)row * KP + (n1 - seg1 * 3074)] = v1;
        }
    }
}

// ================= attention: one q-row per block ================================
__global__ __launch_bounds__(256) void k_attn2() {
    int r = blockIdx.x;
    int b = r / N_;
    int t = threadIdx.x, w = t >> 5, lane = t & 31;
    __shared__ float qs[KP];
    __shared__ float sc[N_];

    float4* qs4 = (float4*)qs;
    const float4* qp = (const float4*)&g_q[(size_t)r*KP];
    for (int u = t; u < KP/4; u += 256) qs4[u] = qp[u];
    __syncthreads();

    float scale = rsqrtf((float)D_);
    for (int kn = w; kn < N_; kn += 8) {
        const float4* kp = (const float4*)&g_k[(size_t)(b*N_ + kn)*KP];
        float acc = 0.f;
        for (int u = lane; u < KP/4; u += 32) {
            float4 a = qs4[u], c = kp[u];
            acc += a.x*c.x + a.y*c.y + a.z*c.z + a.w*c.w;
        }
        #pragma unroll
        for (int o = 16; o > 0; o >>= 1) acc += __shfl_down_sync(0xffffffffu, acc, o);
        if (lane == 0) sc[kn] = acc * scale;
    }
    __syncthreads();

    if (w == 0) {
        float v0 = (lane      < N_) ? sc[lane]      : -1e30f;
        float v1 = (lane + 32 < N_) ? sc[lane + 32] : -1e30f;
        float v2 = (lane + 64 < N_) ? sc[lane + 64] : -1e30f;
        float mx = fmaxf(v0, fmaxf(v1, v2));
        #pragma unroll
        for (int o = 16; o > 0; o >>= 1) mx = fmaxf(mx, __shfl_xor_sync(0xffffffffu, mx, o));
        float e0 = (lane      < N_) ? expf(v0 - mx) : 0.f;
        float e1 = (lane + 32 < N_) ? expf(v1 - mx) : 0.f;
        float e2 = (lane + 64 < N_) ? expf(v2 - mx) : 0.f;
        float s = e0 + e1 + e2;
        #pragma unroll
        for (int o = 16; o > 0; o >>= 1) s += __shfl_xor_sync(0xffffffffu, s, o);
        float inv = 1.f / s;
        if (lane      < N_) sc[lane]      = e0 * inv;
        if (lane + 32 < N_) sc[lane + 32] = e1 * inv;
        if (lane + 64 < N_) sc[lane + 64] = e2 * inv;
    }
    __syncthreads();

    char* cbase = (char*)g_avc;
    uint32_t lrow = (uint32_t)(r * 128);
    const float* vb = &g_v[(size_t)b*N_*KP];
    for (int gidx = t; gidx < KP/8; gidx += 256) {
        int d0 = gidx * 8;
        float a8[8] = {0.f,0.f,0.f,0.f,0.f,0.f,0.f,0.f};
        #pragma unroll 4
        for (int k = 0; k < N_; k++) {
            const float4* vp = (const float4*)(vb + (size_t)k*KP + d0);
            float4 v0 = vp[0], v1 = vp[1];
            float sck = sc[k];
            a8[0] += sck*v0.x; a8[1] += sck*v0.y; a8[2] += sck*v0.z; a8[3] += sck*v0.w;
            a8[4] += sck*v1.x; a8[5] += sck*v1.y; a8[6] += sck*v1.z; a8[7] += sck*v1.w;
        }
        uint32_t loc = lrow + (uint32_t)((d0 & 63) * 2);
        *(uint4*)(cbase + (size_t)(d0 >> 6) * CHA + SW128(loc)) = pack8(a8);
    }
}

// ================= layernorm: LN(in0 + Σ partials + pbias) ======================
__global__ void k_ln(const float* __restrict__ in0,
                     const float* __restrict__ part, int partW, int S,
                     const float* __restrict__ pbias,
                     const float* __restrict__ g, const float* __restrict__ bta,
                     float* __restrict__ outF, __nv_bfloat16* __restrict__ outC) {
    int row = blockIdx.x;
    __shared__ float srow[D_];
    __shared__ float red[256];
    int t = threadIdx.x;
    float lsum = 0.f;
    for (int d = t; d < D_; d += 256) {
        float v = in0[(size_t)row*KP + d] + pbias[d];
        for (int z = 0; z < S; z++)
            v += part[((size_t)z*M_ + row)*partW + d];
        srow[d] = v; lsum += v;
    }
    red[t] = lsum; __syncthreads();
    for (int s = 128; s >= 1; s >>= 1) { if (t < s) red[t] += red[t+s]; __syncthreads(); }
    float mean = red[0] * (1.f/(float)D_);
    __syncthreads();
    float lsq = 0.f;
    for (int d = t; d < D_; d += 256) { float u = srow[d] - mean; lsq += u*u; }
    red[t] = lsq; __syncthreads();
    for (int s = 128; s >= 1; s >>= 1) { if (t < s) red[t] += red[t+s]; __syncthreads(); }
    float rstd = rsqrtf(red[0] * (1.f/(float)D_) + 1e-5f);
    __syncthreads();

    char* cbase = (char*)outC;
    uint32_t lrow = (uint32_t)(row * 128);
    for (int u = t; u < KP/8; u += 256) {
        int d0 = u * 8;
        float v[8];
        #pragma unroll
        for (int e = 0; e < 8; e++) {
            int d = d0 + e;
            v[e] = (d < D_) ? (g[d] * ((srow[d] - mean) * rstd) + bta[d]) : 0.f;
        }
        float4* fp = (float4*)&outF[(size_t)row*KP + d0];
        fp[0] = make_float4(v[0], v[1], v[2], v[3]);
        fp[1] = make_float4(v[4], v[5], v[6], v[7]);
        uint32_t loc = lrow + (uint32_t)((d0 & 63) * 2);
        *(uint4*)(cbase + (size_t)(d0 >> 6) * CHA + SW128(loc)) = pack8(v);
    }
}

// ================= h = relu(Σ partials + l1b) -> chunked bf16 ====================
__global__ void k_hred(const float* __restrict__ bias) {
    int row = blockIdx.x;
    int t = threadIdx.x;
    int d0 = t * 8;
    float v[8];
    #pragma unroll
    for (int e = 0; e < 8; e++) v[e] = bias[d0 + e];
    #pragma unroll
    for (int z = 0; z < S_L1; z++) {
        const float4* p = (const float4*)&g_partH[((size_t)z*M_ + row)*PW_L1 + d0];
        float4 a = p[0], b = p[1];
        v[0]+=a.x; v[1]+=a.y; v[2]+=a.z; v[3]+=a.w;
        v[4]+=b.x; v[5]+=b.y; v[6]+=b.z; v[7]+=b.w;
    }
    #pragma unroll
    for (int e = 0; e < 8; e++) v[e] = fmaxf(v[e], 0.f);
    uint32_t loc = (uint32_t)(row * 128 + (d0 & 63) * 2);
    *(uint4*)((char*)g_hc + (size_t)(d0 >> 6) * CHA + SW128(loc)) = pack8(v);
}

// ================= update: o = Σ partials + ob ==================================
__global__ void k_update(const float* __restrict__ ob, float* __restrict__ dout, int iter) {
    int row = blockIdx.x;
    int t = threadIdx.x;
    for (int c = t; c < C_; c += 256) {
        float o = ob[c];
        #pragma unroll
        for (int z = 0; z < S_OW; z++)
            o += g_partO[((size_t)z*M_ + row)*PW_OW + c];
        g_preq[row*C_ + c] += o;
    }
    if (t == 0) {
        float oy = ob[C_], ox = ob[C_ + 1];
        #pragma unroll
        for (int z = 0; z < S_OW; z++) {
            oy += g_partO[((size_t)z*M_ + row)*PW_OW + C_];
            ox += g_partO[((size_t)z*M_ + row)*PW_OW + C_ + 1];
        }
        float ny = fminf(fmaxf(g_curr[row*2]   + oy, 0.f), 223.f);
        float nx = fminf(fmaxf(g_curr[row*2+1] + ox, 0.f), 223.f);
        g_curr[row*2]   = ny;
        g_curr[row*2+1] = nx;
        dout[iter*(B_*N_*2) + row*2]     = ny;
        dout[iter*(B_*N_*2) + row*2 + 1] = nx;
    }
}

// ================= launch =======================================================
extern "C" void kernel_launch(void* const* d_in, const int* in_sizes, int n_in,
                              void* d_out, int out_size) {
    (void)in_sizes; (void)n_in; (void)out_size;
    const float* pre_f   = (const float*)d_in[0];
    const float* curr_f  = (const float*)d_in[1];
    const float* first_f = (const float*)d_in[2];
    const int*   prev_b  = (const int*)  d_in[3];
    const int*   first_b = (const int*)  d_in[4];
    const float* lng = (const float*)d_in[5];
    const float* lnb = (const float*)d_in[6];
    const float* ipw = (const float*)d_in[7];
    const float* ipb = (const float*)d_in[8];
    const float* opw = (const float*)d_in[9];
    const float* opb = (const float*)d_in[10];
    const float* n1g = (const float*)d_in[11];
    const float* n1b = (const float*)d_in[12];
    const float* l1w = (const float*)d_in[13];
    const float* l1b = (const float*)d_in[14];
    const float* l2w = (const float*)d_in[15];
    const float* l2b = (const float*)d_in[16];
    const float* n2g = (const float*)d_in[17];
    const float* n2b = (const float*)d_in[18];
    const float* ow  = (const float*)d_in[19];
    const float* ob  = (const float*)d_in[20];

    cudaFuncSetAttribute(k_gemm, cudaFuncAttributeMaxDynamicSharedMemorySize, GEMM_SMEM);

    __nv_bfloat16 *p_ipw, *p_opw, *p_l1w, *p_l2w, *p_oww;
    cudaGetSymbolAddress((void**)&p_ipw, g_ipw);
    cudaGetSymbolAddress((void**)&p_opw, g_opw);
    cudaGetSymbolAddress((void**)&p_l1w, g_l1w);
    cudaGetSymbolAddress((void**)&p_l2w, g_l2w);
    cudaGetSymbolAddress((void**)&p_oww, g_oww);

    float *p_tokens, *p_x, *p_partQ, *p_partD, *p_partH, *p_partO;
    cudaGetSymbolAddress((void**)&p_tokens, g_tokens);
    cudaGetSymbolAddress((void**)&p_x,      g_x);
    cudaGetSymbolAddress((void**)&p_partQ,  g_partQ);
    cudaGetSymbolAddress((void**)&p_partD,  g_partD);
    cudaGetSymbolAddress((void**)&p_partH,  g_partH);
    cudaGetSymbolAddress((void**)&p_partO,  g_partO);

    __nv_bfloat16 *p_tokc, *p_avc, *p_xc, *p_hc, *p_x2c;
    cudaGetSymbolAddress((void**)&p_tokc, g_tokc);
    cudaGetSymbolAddress((void**)&p_avc,  g_avc);
    cudaGetSymbolAddress((void**)&p_xc,   g_xc);
    cudaGetSymbolAddress((void**)&p_hc,   g_hc);
    cudaGetSymbolAddress((void**)&p_x2c,  g_x2c);

    k_wconv<<<18944, 128>>>(ipw, opw, l1w, l2w, ow);
    k_gather<<<M_, 256>>>(pre_f, first_f, prev_b, first_b);

    dim3 gip(T_IP, S_IP);   // 146
    dim3 gop(T_OP, S_OP);   // 150
    dim3 gl1(T_L1, S_L1);   // 144
    dim3 gl2(T_L2, S_L2);   // 150
    dim3 gow(T_OW, S_OW);   // 144

    for (int it = 0; it < REFINE_; it++) {
        k_tokens<<<M_, 256>>>(curr_f, lng, lnb);
        k_gemm<<<gip, 256, GEMM_SMEM>>>(p_tokc, p_ipw, KC_D, NP_IP, p_partQ, PW_Q);
        k_qkvred<<<M_, 256>>>(ipb);
        k_attn2<<<M_, 256>>>();
        k_gemm<<<gop, 256, GEMM_SMEM>>>(p_avc, p_opw, KC_D, NP_OP, p_partD, PW_D);
        k_ln<<<M_, 256>>>(p_tokens, p_partD, PW_D, S_OP, opb, n1g, n1b, p_x, p_xc);
        k_gemm<<<gl1, 256, GEMM_SMEM>>>(p_xc, p_l1w, KC_D, NP_L1, p_partH, PW_L1);
        k_hred<<<M_, 256>>>(l1b);
        k_gemm<<<gl2, 256, GEMM_SMEM>>>(p_hc, p_l2w, KC_F, NP_L2, p_partD, PW_D);
        k_ln<<<M_, 256>>>(p_x, p_partD, PW_D, S_L2, l2b, n2g, n2b, p_x, p_x2c);
        k_gemm<<<gow, 256, GEMM_SMEM>>>(p_x2c, p_oww, KC_D, NP_OW, p_partO, PW_OW);
        k_update<<<M_, 256>>>(ob, (float*)d_out, it);
    }
}

// round 15
// speedup vs baseline: 1.0736x; 1.0736x over previous
#include <cuda_runtime.h>
#include <cuda_bf16.h>
#include <math.h>
#include <stdint.h>

#define B_    2
#define C_    1024
#define N_    80
#define D_    3074
#define KP    3200      // padded K (50 chunks of 64; even for 128-wide stages)
#define TD_   9222
#define DFF_  2048
#define OUTD_ 1026
#define M_    160
#define REFINE_ 3

#define KC_D   50
#define KC_F   32
#define KS_D   25       // 128-wide stages
#define KS_F   16
#define CHA    20480    // A chunk bytes  (160*128)
#define CHW    8192     // W chunk bytes  (64*128)
#define N64_IP 145
#define N64_OP 49
#define N64_L1 32
#define N64_L2 49
#define N64_OW 17

#define S_OP 3
#define S_L1 4
#define S_L2 3
#define S_OW 8
#define PW_D  3136
#define PW_L1 2048
#define PW_OW 1088

// ---------------- chunked+swizzled bf16 weights --------------------------------
__device__ __nv_bfloat16 g_ipw[(size_t)KC_D*N64_IP*4096];
__device__ __nv_bfloat16 g_opw[(size_t)KC_D*N64_OP*4096];
__device__ __nv_bfloat16 g_l1w[(size_t)KC_D*N64_L1*4096];
__device__ __nv_bfloat16 g_l2w[(size_t)KC_F*N64_L2*4096];
__device__ __nv_bfloat16 g_oww[(size_t)KC_D*N64_OW*4096];

// ---------------- chunked+swizzled bf16 activations (GEMM A-side) --------------
__device__ __nv_bfloat16 g_tokc[(size_t)KC_D*10240];
__device__ __nv_bfloat16 g_avc [(size_t)KC_D*10240];
__device__ __nv_bfloat16 g_xc  [(size_t)KC_D*10240];
__device__ __nv_bfloat16 g_hc  [(size_t)KC_F*10240];
__device__ __nv_bfloat16 g_x2c [(size_t)KC_D*10240];

// ---------------- fp32 activations + split-K partials --------------------------
__device__ float g_preq  [M_*C_];
__device__ float g_firstq[M_*C_];
__device__ float g_curr  [M_*2];
__device__ float g_pe    [N_*D_];
__device__ float g_tokens[M_*KP];
__device__ float g_q     [M_*KP];
__device__ float g_k     [M_*KP];
__device__ float g_v     [M_*KP];
__device__ float g_x     [M_*KP];
__device__ float g_partD [(size_t)S_OP*M_*PW_D];
__device__ float g_partH [(size_t)S_L1*M_*PW_L1];
__device__ float g_partO [(size_t)S_OW*M_*PW_OW];

// ================= helpers =======================================================
__device__ __forceinline__ uint32_t smem_u32(const void* p) {
    uint32_t a;
    asm("{ .reg .u64 t; cvta.to.shared.u64 t, %1; cvt.u32.u64 %0, t; }" : "=r"(a) : "l"(p));
    return a;
}

#define SW128(bo) ((bo) ^ (((bo) >> 3) & 0x70))

__device__ __forceinline__ void mbar_init(uint32_t mbar, uint32_t cnt) {
    asm volatile("mbarrier.init.shared.b64 [%0], %1;" :: "r"(mbar), "r"(cnt) : "memory");
}
__device__ __forceinline__ void mbar_expect(uint32_t mbar, uint32_t bytes) {
    asm volatile("mbarrier.arrive.expect_tx.shared.b64 _, [%0], %1;"
                 :: "r"(mbar), "r"(bytes) : "memory");
}
__device__ __forceinline__ void mbar_wait(uint32_t mbar, uint32_t parity) {
    asm volatile(
        "{\n\t"
        ".reg .pred P1;\n\t"
        "LAB_%=:\n\t"
        "mbarrier.try_wait.parity.acquire.cta.shared::cta.b64 P1, [%0], %1, 0x989680;\n\t"
        "@P1 bra.uni DONE_%=;\n\t"
        "bra.uni LAB_%=;\n\t"
        "DONE_%=:\n\t"
        "}"
        :: "r"(mbar), "r"(parity) : "memory");
}
__device__ __forceinline__ void fence_async() {
    asm volatile("fence.proxy.async.shared::cta;" ::: "memory");
}
__device__ __forceinline__ void bulk_ld(uint32_t dst, const void* src, uint32_t bytes, uint32_t bar) {
    asm volatile(
        "cp.async.bulk.shared::cluster.global.mbarrier::complete_tx::bytes [%0], [%1], %2, [%3];"
        :: "r"(dst), "l"(src), "r"(bytes), "r"(bar) : "memory");
}
__device__ __forceinline__ void ldsm4(uint32_t* r, uint32_t addr) {
    asm volatile("ldmatrix.sync.aligned.m8n8.x4.shared.b16 {%0,%1,%2,%3}, [%4];"
                 : "=r"(r[0]), "=r"(r[1]), "=r"(r[2]), "=r"(r[3]) : "r"(addr));
}
__device__ __forceinline__ void mma16816(float c[4], const uint32_t a[4],
                                         uint32_t b0, uint32_t b1) {
    asm volatile(
        "mma.sync.aligned.m16n8k16.row.col.f32.bf16.bf16.f32 "
        "{%0,%1,%2,%3},{%4,%5,%6,%7},{%8,%9},{%0,%1,%2,%3};"
        : "+f"(c[0]), "+f"(c[1]), "+f"(c[2]), "+f"(c[3])
        : "r"(a[0]), "r"(a[1]), "r"(a[2]), "r"(a[3]), "r"(b0), "r"(b1));
}

// ================= bilinear sampling ============================================
struct Bil { int i0,i1,j0,j1; float w00,w01,w10,w11; };

__device__ __forceinline__ Bil make_bil(int py, int px) {
    float cy = ((float)py + 0.5f) * (14.0f/224.0f) - 0.5f;
    float cx = ((float)px + 0.5f) * (14.0f/224.0f) - 0.5f;
    float fy = floorf(cy), fx = floorf(cx);
    float ay = cy - fy,    ax = cx - fx;
    int y0 = (int)fy, x0 = (int)fx;
    Bil b;
    b.i0 = min(13, max(0, y0));   b.i1 = min(13, max(0, y0+1));
    b.j0 = min(13, max(0, x0));   b.j1 = min(13, max(0, x0+1));
    b.w00 = (1.f-ay)*(1.f-ax); b.w01 = (1.f-ay)*ax;
    b.w10 = ay*(1.f-ax);       b.w11 = ay*ax;
    return b;
}

__device__ __forceinline__ float bil_sample(const float* __restrict__ f, int c, const Bil& b) {
    const float* p = f + c*196;
    return b.w00*p[b.i0*14 + b.j0] + b.w01*p[b.i0*14 + b.j1]
         + b.w10*p[b.i1*14 + b.j0] + b.w11*p[b.i1*14 + b.j1];
}

__device__ __forceinline__ uint4 pack8(const float* v) {
    uint4 r;
    __nv_bfloat162 b0 = __float22bfloat162_rn(make_float2(v[0], v[1]));
    __nv_bfloat162 b1 = __float22bfloat162_rn(make_float2(v[2], v[3]));
    __nv_bfloat162 b2 = __float22bfloat162_rn(make_float2(v[4], v[5]));
    __nv_bfloat162 b3 = __float22bfloat162_rn(make_float2(v[6], v[7]));
    r.x = *(uint32_t*)&b0; r.y = *(uint32_t*)&b1;
    r.z = *(uint32_t*)&b2; r.w = *(uint32_t*)&b3;
    return r;
}

// ================= merged prologue: gather + pe + wconv =========================
// blocks [0,160): gather/align; [160,240): pe; [240, 240+18688): wconv
__global__ void k_prolog(const float* __restrict__ pre_f,
                         const float* __restrict__ first_f,
                         const int* __restrict__ prev,
                         const int* __restrict__ first,
                         const float* __restrict__ ipw, const float* __restrict__ opw,
                         const float* __restrict__ l1w, const float* __restrict__ l2w,
                         const float* __restrict__ oww) {
    __shared__ int sp[N_*2], sf[N_*2];
    __shared__ int skey[256];
    int blk = blockIdx.x;
    int t = threadIdx.x;

    if (blk < 160) {
        // ---- gather with inline roll alignment ----
        int row = blk;
        int b = row / N_, j = row % N_;
        for (int i = t; i < N_*2; i += 256) {
            sp[i] = prev [b*N_*2 + i];
            sf[i] = first[b*N_*2 + i];
        }
        __syncthreads();
        int key = 0x7FFFFFFF;
        if (t < N_) {
            int acc = 0;
            for (int q = 0; q < N_; q++) {
                int qq = (q - t + N_) % N_;
                acc += abs(sp[q*2]   - sf[qq*2]);
                acc += abs(sp[q*2+1] - sf[qq*2+1]);
            }
            key = acc * 128 + t;
        }
        skey[t] = key; __syncthreads();
        for (int s = 128; s >= 1; s >>= 1) {
            if (t < s) skey[t] = min(skey[t], skey[t+s]);
            __syncthreads();
        }
        int best = skey[0] & 127;

        int jj = (j - best + N_) % N_;
        int py = sp[j*2], px = sp[j*2+1];
        Bil bp = make_bil(py, px);
        Bil bf = make_bil(sf[jj*2], sf[jj*2+1]);
        const float* pf = pre_f   + b*C_*196;
        const float* ff = first_f + b*C_*196;
        for (int c = t; c < C_; c += 256) {
            g_preq  [row*C_ + c] = bil_sample(pf, c, bp);
            g_firstq[row*C_ + c] = bil_sample(ff, c, bf);
        }
        if (t < KP - D_) {
            g_q[(size_t)row*KP + D_ + t] = 0.f;
            g_k[(size_t)row*KP + D_ + t] = 0.f;
            g_v[(size_t)row*KP + D_ + t] = 0.f;
        }
        if (t == 0) {
            g_curr[row*2]   = (float)py;
            g_curr[row*2+1] = (float)px;
        }
        return;
    }
    if (blk < 240) {
        // ---- positional encoding table ----
        int n = blk - 160;
        for (int d = t; d < D_; d += 256) {
            int k2 = d & ~1;
            float div = expf((float)k2 * (-9.210340371976184f / (float)D_));
            float arg = (float)n * div;
            g_pe[n*D_ + d] = (d & 1) ? cosf(arg) : sinf(arg);
        }
        return;
    }

    // ---- weight conversion ----
    int b = blk - 240;
    const float* src; __nv_bfloat16* dst;
    int N, K, KC, N64, n;
    if (b < 9280)       { n = b;         src = ipw; dst = g_ipw; N = TD_;  K = D_;   KC = KC_D; N64 = N64_IP; }
    else if (b < 12416) { n = b - 9280;  src = opw; dst = g_opw; N = D_;   K = D_;   KC = KC_D; N64 = N64_OP; }
    else if (b < 14464) { n = b - 12416; src = l1w; dst = g_l1w; N = DFF_; K = D_;   KC = KC_D; N64 = N64_L1; }
    else if (b < 17600) { n = b - 14464; src = l2w; dst = g_l2w; N = D_;   K = DFF_; KC = KC_F; N64 = N64_L2; }
    else                { n = b - 17600; src = oww; dst = g_oww; N = OUTD_;K = D_;   KC = KC_D; N64 = N64_OW; }

    bool nok = n < N;
    const float* srow = src + (size_t)n * K;
    char* dbase = (char*)dst + (size_t)(n >> 6) * CHW;
    uint32_t lrow = (uint32_t)((n & 63) * 128);
    size_t kstride = (size_t)N64 * CHW;
    int units = KC * 8;

    for (int u = t; u < units; u += 256) {
        int k0 = u * 8;
        float v[8];
        if (nok && k0 + 8 <= K) {
            float2 f0 = *(const float2*)(srow + k0);
            float2 f1 = *(const float2*)(srow + k0 + 2);
            float2 f2 = *(const float2*)(srow + k0 + 4);
            float2 f3 = *(const float2*)(srow + k0 + 6);
            v[0]=f0.x; v[1]=f0.y; v[2]=f1.x; v[3]=f1.y;
            v[4]=f2.x; v[5]=f2.y; v[6]=f3.x; v[7]=f3.y;
        } else {
            #pragma unroll
            for (int e = 0; e < 8; e++)
                v[e] = (nok && (k0 + e) < K) ? srow[k0 + e] : 0.f;
        }
        uint32_t loc = lrow + (uint32_t)((k0 & 63) * 2);
        *(uint4*)(dbase + (size_t)(k0 >> 6) * kstride + SW128(loc)) = pack8(v);
    }
}

// ================= tokens = LN(concat) + pe(table) ==============================
__global__ void k_tokens(const float* __restrict__ curr_f,
                         const float* __restrict__ lng,
                         const float* __restrict__ lnb) {
    int row = blockIdx.x;
    int b = row / N_, n = row % N_;
    __shared__ float srow[D_];
    __shared__ float red[256];
    int t = threadIdx.x;

    float cy = g_curr[row*2], cx = g_curr[row*2+1];
    int py = (int)cy, px = (int)cx;
    Bil bb = make_bil(py, px);
    const float* cf = curr_f + b*C_*196;

    float lsum = 0.f;
    for (int d = t; d < D_; d += 256) {
        float v;
        if      (d < C_)        v = g_preq[row*C_ + d];
        else if (d < 2*C_)      v = bil_sample(cf, d - C_, bb);
        else if (d == 2*C_)     v = cy;
        else if (d == 2*C_+1)   v = cx;
        else                    v = g_firstq[row*C_ + (d - (2*C_+2))];
        srow[d] = v;
        lsum += v;
    }
    red[t] = lsum; __syncthreads();
    for (int s = 128; s >= 1; s >>= 1) { if (t < s) red[t] += red[t+s]; __syncthreads(); }
    float mean = red[0] * (1.f/(float)D_);
    __syncthreads();

    float lsq = 0.f;
    for (int d = t; d < D_; d += 256) { float u = srow[d] - mean; lsq += u*u; }
    red[t] = lsq; __syncthreads();
    for (int s = 128; s >= 1; s >>= 1) { if (t < s) red[t] += red[t+s]; __syncthreads(); }
    float rstd = rsqrtf(red[0] * (1.f/(float)D_) + 1e-5f);
    __syncthreads();

    char* cbase = (char*)g_tokc;
    uint32_t lrow = (uint32_t)(row * 128);
    const float* perow = &g_pe[n*D_];
    for (int u = t; u < KP/8; u += 256) {
        int d0 = u * 8;
        float v[8];
        #pragma unroll
        for (int e = 0; e < 8; e++) {
            int d = d0 + e;
            v[e] = (d < D_) ? (lng[d] * ((srow[d] - mean) * rstd) + lnb[d] + perow[d]) : 0.f;
        }
        float4* fp = (float4*)&g_tokens[(size_t)row*KP + d0];
        fp[0] = make_float4(v[0], v[1], v[2], v[3]);
        fp[1] = make_float4(v[4], v[5], v[6], v[7]);
        uint32_t loc = lrow + (uint32_t)((d0 & 63) * 2);
        *(uint4*)(cbase + (size_t)(d0 >> 6) * CHA + SW128(loc)) = pack8(v);
    }
}

// ================= GEMM: 128-wide stages, reg-double-buffered fragments =========
#define NSTG 3
#define STAGE_B (2*CHA + 2*CHW)              // 57344
#define GEMM_SMEM (NSTG*STAGE_B + 64)        // 172096

__global__ __launch_bounds__(256) void k_gemm(
    const __nv_bfloat16* __restrict__ Ac,
    const __nv_bfloat16* __restrict__ Wc,
    int KS, int N64,
    const float* __restrict__ bias,
    float* __restrict__ Part, int ldo, int mode,
    float* __restrict__ oq, float* __restrict__ okk, float* __restrict__ ov)
{
    extern __shared__ char sm[];
    uint32_t smb = smem_u32(sm);
    uint32_t mb = smb + NSTG * STAGE_B;

    int t = threadIdx.x;
    int warp = t >> 5, lane = t & 31;
    int wm = (warp >> 2) * 80;
    int wn = (warp & 3) * 16;
    int qr = lane >> 2, qc2 = (lane & 3) * 2;
    int nb = blockIdx.x, n0 = nb * 64;
    int z = blockIdx.y, S = gridDim.y;
    int ks0 = (KS * z) / S, ks1 = (KS * (z + 1)) / S;
    int nst = ks1 - ks0;

    int sub   = lane & 7;
    int m_off = ((lane >> 3) & 1) * 8 + sub;
    int k_off = (lane >> 4) * 8;
    uint32_t swz = (uint32_t)(sub * 16);
    uint32_t w_row_off = (uint32_t)((wn + m_off) * 128);

    if (t == 0) {
        mbar_init(mb, 1); mbar_init(mb + 8, 1); mbar_init(mb + 16, 1);
        fence_async();
    }
    __syncthreads();

    float acc[5][2][4];
    #pragma unroll
    for (int i = 0; i < 5; i++)
        #pragma unroll
        for (int j = 0; j < 2; j++)
            #pragma unroll
            for (int r = 0; r < 4; r++) acc[i][j][r] = 0.f;

    if (t == 0) {
        #pragma unroll
        for (int p = 0; p < 2; p++) {
            if (p >= nst) break;
            int kg = ks0 + p;
            uint32_t s = p, bar = mb + s*8;
            mbar_expect(bar, STAGE_B);
            bulk_ld(smb + s*STAGE_B, (const char*)Ac + (size_t)(2*kg)*CHA, 2*CHA, bar);
            bulk_ld(smb + s*STAGE_B + 2*CHA,
                    (const char*)Wc + ((size_t)(2*kg)*N64 + nb)*CHW, CHW, bar);
            bulk_ld(smb + s*STAGE_B + 2*CHA + CHW,
                    (const char*)Wc + ((size_t)(2*kg+1)*N64 + nb)*CHW, CHW, bar);
        }
    }

    uint32_t amA[5][4], bmA[4], amB[5][4], bmB[4];

    for (int l = 0; l < nst; l++) {
        int s = l % NSTG;
        mbar_wait(mb + s*8, (uint32_t)((l/NSTG) & 1));
        if (t == 0 && l + 2 < nst) {
            int l2i = l + 2;
            int kg = ks0 + l2i;
            uint32_t s2 = l2i % NSTG, bar = mb + s2*8;
            mbar_expect(bar, STAGE_B);
            bulk_ld(smb + s2*STAGE_B, (const char*)Ac + (size_t)(2*kg)*CHA, 2*CHA, bar);
            bulk_ld(smb + s2*STAGE_B + 2*CHA,
                    (const char*)Wc + ((size_t)(2*kg)*N64 + nb)*CHW, CHW, bar);
            bulk_ld(smb + s2*STAGE_B + 2*CHA + CHW,
                    (const char*)Wc + ((size_t)(2*kg+1)*N64 + nb)*CHW, CHW, bar);
        }
        uint32_t st_b = smb + s*STAGE_B;

        #define LDP(BUFam, BUFbm, p) do { \
            int c2_ = (p) >> 2, kk_ = ((p) & 3) * 16; \
            uint32_t as_ = st_b + (uint32_t)(c2_ * CHA); \
            uint32_t ws_ = st_b + (uint32_t)(2*CHA + c2_ * CHW); \
            uint32_t col_ = ((uint32_t)((kk_ + k_off) * 2)) ^ swz; \
            ldsm4(BUFam[0], as_ + (uint32_t)((wm +   0 + m_off) * 128) + col_); \
            ldsm4(BUFam[1], as_ + (uint32_t)((wm +  16 + m_off) * 128) + col_); \
            ldsm4(BUFam[2], as_ + (uint32_t)((wm +  32 + m_off) * 128) + col_); \
            ldsm4(BUFam[3], as_ + (uint32_t)((wm +  48 + m_off) * 128) + col_); \
            ldsm4(BUFam[4], as_ + (uint32_t)((wm +  64 + m_off) * 128) + col_); \
            ldsm4(BUFbm,    ws_ + w_row_off + col_); \
        } while (0)

        #define MMAP(BUFam, BUFbm) do { \
            _Pragma("unroll") \
            for (int i_ = 0; i_ < 5; i_++) { \
                mma16816(acc[i_][0], BUFam[i_], BUFbm[0], BUFbm[2]); \
                mma16816(acc[i_][1], BUFam[i_], BUFbm[1], BUFbm[3]); \
            } \
        } while (0)

        LDP(amA, bmA, 0);
        #pragma unroll
        for (int p = 0; p < 8; p += 2) {
            if (p + 1 < 8) LDP(amB, bmB, p + 1);
            MMAP(amA, bmA);
            if (p + 2 < 8) LDP(amA, bmA, p + 2);
            MMAP(amB, bmB);
        }
        #undef LDP
        #undef MMAP
        __syncthreads();
    }

    if (mode == 3) {
        float* dst = Part + (size_t)z * M_ * ldo;
        #pragma unroll
        for (int i = 0; i < 5; i++) {
            #pragma unroll
            for (int j = 0; j < 2; j++) {
                int n = n0 + wn + j*8 + qc2;
                #pragma unroll
                for (int h = 0; h < 2; h++) {
                    int m = wm + i*16 + qr + h*8;
                    dst[(size_t)m * ldo + n]     = acc[i][j][h*2 + 0];
                    dst[(size_t)m * ldo + n + 1] = acc[i][j][h*2 + 1];
                }
            }
        }
    } else {  // mode 2: qkv split + bias
        #pragma unroll
        for (int i = 0; i < 5; i++) {
            #pragma unroll
            for (int j = 0; j < 2; j++) {
                int n = n0 + wn + j*8 + qc2;
                #pragma unroll
                for (int h = 0; h < 2; h++) {
                    int m = wm + i*16 + qr + h*8;
                    #pragma unroll
                    for (int c2 = 0; c2 < 2; c2++) {
                        int nn = n + c2;
                        if (nn >= TD_) continue;
                        float v = acc[i][j][h*2 + c2] + __ldg(&bias[nn]);
                        int seg = (nn >= 6148) ? 2 : (nn >= 3074 ? 1 : 0);
                        int col = nn - seg * 3074;
                        float* dstq = (seg == 0) ? oq : (seg == 1 ? okk : ov);
                        dstq[(size_t)m * KP + col] = v;
                    }
                }
            }
        }
    }
}

// ================= attention: one q-row per block ================================
__global__ __launch_bounds__(256) void k_attn2() {
    int r = blockIdx.x;
    int b = r / N_;
    int t = threadIdx.x, w = t >> 5, lane = t & 31;
    __shared__ float qs[KP];
    __shared__ float sc[N_];

    float4* qs4 = (float4*)qs;
    const float4* qp = (const float4*)&g_q[(size_t)r*KP];
    for (int u = t; u < KP/4; u += 256) qs4[u] = qp[u];
    __syncthreads();

    float scale = rsqrtf((float)D_);
    for (int kn = w; kn < N_; kn += 8) {
        const float4* kp = (const float4*)&g_k[(size_t)(b*N_ + kn)*KP];
        float acc = 0.f;
        for (int u = lane; u < KP/4; u += 32) {
            float4 a = qs4[u], c = kp[u];
            acc += a.x*c.x + a.y*c.y + a.z*c.z + a.w*c.w;
        }
        #pragma unroll
        for (int o = 16; o > 0; o >>= 1) acc += __shfl_down_sync(0xffffffffu, acc, o);
        if (lane == 0) sc[kn] = acc * scale;
    }
    __syncthreads();

    if (w == 0) {
        float v0 = (lane      < N_) ? sc[lane]      : -1e30f;
        float v1 = (lane + 32 < N_) ? sc[lane + 32] : -1e30f;
        float v2 = (lane + 64 < N_) ? sc[lane + 64] : -1e30f;
        float mx = fmaxf(v0, fmaxf(v1, v2));
        #pragma unroll
        for (int o = 16; o > 0; o >>= 1) mx = fmaxf(mx, __shfl_xor_sync(0xffffffffu, mx, o));
        float e0 = (lane      < N_) ? expf(v0 - mx) : 0.f;
        float e1 = (lane + 32 < N_) ? expf(v1 - mx) : 0.f;
        float e2 = (lane + 64 < N_) ? expf(v2 - mx) : 0.f;
        float s = e0 + e1 + e2;
        #pragma unroll
        for (int o = 16; o > 0; o >>= 1) s += __shfl_xor_sync(0xffffffffu, s, o);
        float inv = 1.f / s;
        if (lane      < N_) sc[lane]      = e0 * inv;
        if (lane + 32 < N_) sc[lane + 32] = e1 * inv;
        if (lane + 64 < N_) sc[lane + 64] = e2 * inv;
    }
    __syncthreads();

    char* cbase = (char*)g_avc;
    uint32_t lrow = (uint32_t)(r * 128);
    const float* vb = &g_v[(size_t)b*N_*KP];
    for (int gidx = t; gidx < KP/8; gidx += 256) {
        int d0 = gidx * 8;
        float a8[8] = {0.f,0.f,0.f,0.f,0.f,0.f,0.f,0.f};
        #pragma unroll 4
        for (int k = 0; k < N_; k++) {
            const float4* vp = (const float4*)(vb + (size_t)k*KP + d0);
            float4 v0 = vp[0], v1 = vp[1];
            float sck = sc[k];
            a8[0] += sck*v0.x; a8[1] += sck*v0.y; a8[2] += sck*v0.z; a8[3] += sck*v0.w;
            a8[4] += sck*v1.x; a8[5] += sck*v1.y; a8[6] += sck*v1.z; a8[7] += sck*v1.w;
        }
        uint32_t loc = lrow + (uint32_t)((d0 & 63) * 2);
        *(uint4*)(cbase + (size_t)(d0 >> 6) * CHA + SW128(loc)) = pack8(a8);
    }
}

// ================= layernorm: LN(in0 + Σ partials + pbias) ======================
__global__ void k_ln(const float* __restrict__ in0,
                     const float* __restrict__ part, int partW, int S,
                     const float* __restrict__ pbias,
                     const float* __restrict__ g, const float* __restrict__ bta,
                     float* __restrict__ outF, __nv_bfloat16* __restrict__ outC) {
    int row = blockIdx.x;
    __shared__ float srow[D_];
    __shared__ float red[256];
    int t = threadIdx.x;
    float lsum = 0.f;
    for (int d = t; d < D_; d += 256) {
        float v = in0[(size_t)row*KP + d] + pbias[d];
        for (int z = 0; z < S; z++)
            v += part[((size_t)z*M_ + row)*partW + d];
        srow[d] = v; lsum += v;
    }
    red[t] = lsum; __syncthreads();
    for (int s = 128; s >= 1; s >>= 1) { if (t < s) red[t] += red[t+s]; __syncthreads(); }
    float mean = red[0] * (1.f/(float)D_);
    __syncthreads();
    float lsq = 0.f;
    for (int d = t; d < D_; d += 256) { float u = srow[d] - mean; lsq += u*u; }
    red[t] = lsq; __syncthreads();
    for (int s = 128; s >= 1; s >>= 1) { if (t < s) red[t] += red[t+s]; __syncthreads(); }
    float rstd = rsqrtf(red[0] * (1.f/(float)D_) + 1e-5f);
    __syncthreads();

    char* cbase = (char*)outC;
    uint32_t lrow = (uint32_t)(row * 128);
    for (int u = t; u < KP/8; u += 256) {
        int d0 = u * 8;
        float v[8];
        #pragma unroll
        for (int e = 0; e < 8; e++) {
            int d = d0 + e;
            v[e] = (d < D_) ? (g[d] * ((srow[d] - mean) * rstd) + bta[d]) : 0.f;
        }
        float4* fp = (float4*)&outF[(size_t)row*KP + d0];
        fp[0] = make_float4(v[0], v[1], v[2], v[3]);
        fp[1] = make_float4(v[4], v[5], v[6], v[7]);
        uint32_t loc = lrow + (uint32_t)((d0 & 63) * 2);
        *(uint4*)(cbase + (size_t)(d0 >> 6) * CHA + SW128(loc)) = pack8(v);
    }
}

// ================= h = relu(Σ partials + l1b) -> chunked bf16 ====================
__global__ void k_hred(const float* __restrict__ bias) {
    int row = blockIdx.x;
    int t = threadIdx.x;
    int d0 = t * 8;
    float v[8];
    #pragma unroll
    for (int e = 0; e < 8; e++) v[e] = bias[d0 + e];
    #pragma unroll
    for (int z = 0; z < S_L1; z++) {
        const float4* p = (const float4*)&g_partH[((size_t)z*M_ + row)*PW_L1 + d0];
        float4 a = p[0], b = p[1];
        v[0]+=a.x; v[1]+=a.y; v[2]+=a.z; v[3]+=a.w;
        v[4]+=b.x; v[5]+=b.y; v[6]+=b.z; v[7]+=b.w;
    }
    #pragma unroll
    for (int e = 0; e < 8; e++) v[e] = fmaxf(v[e], 0.f);
    uint32_t loc = (uint32_t)(row * 128 + (d0 & 63) * 2);
    *(uint4*)((char*)g_hc + (size_t)(d0 >> 6) * CHA + SW128(loc)) = pack8(v);
}

// ================= update: o = Σ partials + ob ==================================
__global__ void k_update(const float* __restrict__ ob, float* __restrict__ dout, int iter) {
    int row = blockIdx.x;
    int t = threadIdx.x;
    for (int c = t; c < C_; c += 256) {
        float o = ob[c];
        #pragma unroll
        for (int z = 0; z < S_OW; z++)
            o += g_partO[((size_t)z*M_ + row)*PW_OW + c];
        g_preq[row*C_ + c] += o;
    }
    if (t == 0) {
        float oy = ob[C_], ox = ob[C_ + 1];
        #pragma unroll
        for (int z = 0; z < S_OW; z++) {
            oy += g_partO[((size_t)z*M_ + row)*PW_OW + C_];
            ox += g_partO[((size_t)z*M_ + row)*PW_OW + C_ + 1];
        }
        float ny = fminf(fmaxf(g_curr[row*2]   + oy, 0.f), 223.f);
        float nx = fminf(fmaxf(g_curr[row*2+1] + ox, 0.f), 223.f);
        g_curr[row*2]   = ny;
        g_curr[row*2+1] = nx;
        dout[iter*(B_*N_*2) + row*2]     = ny;
        dout[iter*(B_*N_*2) + row*2 + 1] = nx;
    }
}

// ================= launch =======================================================
extern "C" void kernel_launch(void* const* d_in, const int* in_sizes, int n_in,
                              void* d_out, int out_size) {
    (void)in_sizes; (void)n_in; (void)out_size;
    const float* pre_f   = (const float*)d_in[0];
    const float* curr_f  = (const float*)d_in[1];
    const float* first_f = (const float*)d_in[2];
    const int*   prev_b  = (const int*)  d_in[3];
    const int*   first_b = (const int*)  d_in[4];
    const float* lng = (const float*)d_in[5];
    const float* lnb = (const float*)d_in[6];
    const float* ipw = (const float*)d_in[7];
    const float* ipb = (const float*)d_in[8];
    const float* opw = (const float*)d_in[9];
    const float* opb = (const float*)d_in[10];
    const float* n1g = (const float*)d_in[11];
    const float* n1b = (const float*)d_in[12];
    const float* l1w = (const float*)d_in[13];
    const float* l1b = (const float*)d_in[14];
    const float* l2w = (const float*)d_in[15];
    const float* l2b = (const float*)d_in[16];
    const float* n2g = (const float*)d_in[17];
    const float* n2b = (const float*)d_in[18];
    const float* ow  = (const float*)d_in[19];
    const float* ob  = (const float*)d_in[20];

    cudaFuncSetAttribute(k_gemm, cudaFuncAttributeMaxDynamicSharedMemorySize, GEMM_SMEM);

    __nv_bfloat16 *p_ipw, *p_opw, *p_l1w, *p_l2w, *p_oww;
    cudaGetSymbolAddress((void**)&p_ipw, g_ipw);
    cudaGetSymbolAddress((void**)&p_opw, g_opw);
    cudaGetSymbolAddress((void**)&p_l1w, g_l1w);
    cudaGetSymbolAddress((void**)&p_l2w, g_l2w);
    cudaGetSymbolAddress((void**)&p_oww, g_oww);

    float *p_tokens, *p_q, *p_k, *p_v, *p_x, *p_partD, *p_partH, *p_partO;
    cudaGetSymbolAddress((void**)&p_tokens, g_tokens);
    cudaGetSymbolAddress((void**)&p_q,      g_q);
    cudaGetSymbolAddress((void**)&p_k,      g_k);
    cudaGetSymbolAddress((void**)&p_v,      g_v);
    cudaGetSymbolAddress((void**)&p_x,      g_x);
    cudaGetSymbolAddress((void**)&p_partD,  g_partD);
    cudaGetSymbolAddress((void**)&p_partH,  g_partH);
    cudaGetSymbolAddress((void**)&p_partO,  g_partO);

    __nv_bfloat16 *p_tokc, *p_avc, *p_xc, *p_hc, *p_x2c;
    cudaGetSymbolAddress((void**)&p_tokc, g_tokc);
    cudaGetSymbolAddress((void**)&p_avc,  g_avc);
    cudaGetSymbolAddress((void**)&p_xc,   g_xc);
    cudaGetSymbolAddress((void**)&p_hc,   g_hc);
    cudaGetSymbolAddress((void**)&p_x2c,  g_x2c);

    // merged prologue: gather (160) + pe (80) + wconv (18688)
    k_prolog<<<18928, 256>>>(pre_f, first_f, prev_b, first_b,
                             ipw, opw, l1w, l2w, ow);

    dim3 gip(N64_IP, 1);      // 145
    dim3 gop(N64_OP, S_OP);   // 147
    dim3 gl1(N64_L1, S_L1);   // 128
    dim3 gl2(N64_L2, S_L2);   // 147
    dim3 gow(N64_OW, S_OW);   // 136

    for (int it = 0; it < REFINE_; it++) {
        k_tokens<<<M_, 256>>>(curr_f, lng, lnb);
        k_gemm<<<gip, 256, GEMM_SMEM>>>(p_tokc, p_ipw, KS_D, N64_IP, ipb,
                                        nullptr, 0, 2, p_q, p_k, p_v);
        k_attn2<<<M_, 256>>>();
        k_gemm<<<gop, 256, GEMM_SMEM>>>(p_avc, p_opw, KS_D, N64_OP, nullptr,
                                        p_partD, PW_D, 3, nullptr, nullptr, nullptr);
        k_ln<<<M_, 256>>>(p_tokens, p_partD, PW_D, S_OP, opb, n1g, n1b, p_x, p_xc);
        k_gemm<<<gl1, 256, GEMM_SMEM>>>(p_xc, p_l1w, KS_D, N64_L1, nullptr,
                                        p_partH, PW_L1, 3, nullptr, nullptr, nullptr);
        k_hred<<<M_, 256>>>(l1b);
        k_gemm<<<gl2, 256, GEMM_SMEM>>>(p_hc, p_l2w, KS_F, N64_L2, nullptr,
                                        p_partD, PW_D, 3, nullptr, nullptr, nullptr);
        k_ln<<<M_, 256>>>(p_x, p_partD, PW_D, S_L2, l2b, n2g, n2b, p_x, p_x2c);
        k_gemm<<<gow, 256, GEMM_SMEM>>>(p_x2c, p_oww, KS_D, N64_OW, nullptr,
                                        p_partO, PW_OW, 3, nullptr, nullptr, nullptr);
        k_update<<<M_, 256>>>(ob, (float*)d_out, it);
    }
}

// round 16
// speedup vs baseline: 1.0805x; 1.0064x over previous
#include <cuda_runtime.h>
#include <cuda_bf16.h>
#include <math.h>
#include <stdint.h>

#define B_    2
#define C_    1024
#define N_    80
#define D_    3074
#define KP    3200      // padded K (50 chunks of 64; even for 128-wide stages)
#define TD_   9222
#define DFF_  2048
#define OUTD_ 1026
#define M_    160
#define REFINE_ 3

#define KC_D   50
#define KC_F   32
#define KS_D   25       // 128-wide stages
#define KS_F   16
#define CHA    20480    // A chunk bytes  (160*128)
#define CHW    8192     // W chunk bytes  (64*128)
#define N64_IP 145
#define N64_OP 49
#define N64_L1 32
#define N64_L2 49
#define N64_OW 17

#define S_OP 3
#define S_L1 4
#define S_L2 3
#define S_OW 8
#define PW_D  3136
#define PW_L1 2048
#define PW_OW 1088

// ---------------- chunked+swizzled bf16 weights --------------------------------
__device__ __nv_bfloat16 g_ipw[(size_t)KC_D*N64_IP*4096];
__device__ __nv_bfloat16 g_opw[(size_t)KC_D*N64_OP*4096];
__device__ __nv_bfloat16 g_l1w[(size_t)KC_D*N64_L1*4096];
__device__ __nv_bfloat16 g_l2w[(size_t)KC_F*N64_L2*4096];
__device__ __nv_bfloat16 g_oww[(size_t)KC_D*N64_OW*4096];

// ---------------- chunked+swizzled bf16 activations (GEMM A-side) --------------
__device__ __nv_bfloat16 g_tokc[(size_t)KC_D*10240];
__device__ __nv_bfloat16 g_avc [(size_t)KC_D*10240];
__device__ __nv_bfloat16 g_xc  [(size_t)KC_D*10240];
__device__ __nv_bfloat16 g_hc  [(size_t)KC_F*10240];
__device__ __nv_bfloat16 g_x2c [(size_t)KC_D*10240];

// ---------------- fp32 activations + split-K partials --------------------------
__device__ float g_preq  [M_*C_];
__device__ float g_firstq[M_*C_];
__device__ float g_curr  [M_*2];
__device__ float g_pe    [N_*D_];
__device__ float g_tokens[M_*KP];
__device__ float g_q     [M_*KP];
__device__ float g_k     [M_*KP];
__device__ float g_v     [M_*KP];
__device__ float g_x     [M_*KP];
__device__ float g_sc    [M_*N_];
__device__ float g_partD [(size_t)S_OP*M_*PW_D];
__device__ float g_partH [(size_t)S_L1*M_*PW_L1];
__device__ float g_partO [(size_t)S_OW*M_*PW_OW];

// ================= helpers =======================================================
__device__ __forceinline__ uint32_t smem_u32(const void* p) {
    uint32_t a;
    asm("{ .reg .u64 t; cvta.to.shared.u64 t, %1; cvt.u32.u64 %0, t; }" : "=r"(a) : "l"(p));
    return a;
}

#define SW128(bo) ((bo) ^ (((bo) >> 3) & 0x70))

__device__ __forceinline__ void mbar_init(uint32_t mbar, uint32_t cnt) {
    asm volatile("mbarrier.init.shared.b64 [%0], %1;" :: "r"(mbar), "r"(cnt) : "memory");
}
__device__ __forceinline__ void mbar_expect(uint32_t mbar, uint32_t bytes) {
    asm volatile("mbarrier.arrive.expect_tx.shared.b64 _, [%0], %1;"
                 :: "r"(mbar), "r"(bytes) : "memory");
}
__device__ __forceinline__ void mbar_wait(uint32_t mbar, uint32_t parity) {
    asm volatile(
        "{\n\t"
        ".reg .pred P1;\n\t"
        "LAB_%=:\n\t"
        "mbarrier.try_wait.parity.acquire.cta.shared::cta.b64 P1, [%0], %1, 0x989680;\n\t"
        "@P1 bra.uni DONE_%=;\n\t"
        "bra.uni LAB_%=;\n\t"
        "DONE_%=:\n\t"
        "}"
        :: "r"(mbar), "r"(parity) : "memory");
}
__device__ __forceinline__ void fence_async() {
    asm volatile("fence.proxy.async.shared::cta;" ::: "memory");
}
__device__ __forceinline__ void bulk_ld(uint32_t dst, const void* src, uint32_t bytes, uint32_t bar) {
    asm volatile(
        "cp.async.bulk.shared::cluster.global.mbarrier::complete_tx::bytes [%0], [%1], %2, [%3];"
        :: "r"(dst), "l"(src), "r"(bytes), "r"(bar) : "memory");
}
__device__ __forceinline__ void ldsm4(uint32_t* r, uint32_t addr) {
    asm volatile("ldmatrix.sync.aligned.m8n8.x4.shared.b16 {%0,%1,%2,%3}, [%4];"
                 : "=r"(r[0]), "=r"(r[1]), "=r"(r[2]), "=r"(r[3]) : "r"(addr));
}
__device__ __forceinline__ void mma16816(float c[4], const uint32_t a[4],
                                         uint32_t b0, uint32_t b1) {
    asm volatile(
        "mma.sync.aligned.m16n8k16.row.col.f32.bf16.bf16.f32 "
        "{%0,%1,%2,%3},{%4,%5,%6,%7},{%8,%9},{%0,%1,%2,%3};"
        : "+f"(c[0]), "+f"(c[1]), "+f"(c[2]), "+f"(c[3])
        : "r"(a[0]), "r"(a[1]), "r"(a[2]), "r"(a[3]), "r"(b0), "r"(b1));
}

// ================= bilinear sampling ============================================
struct Bil { int i0,i1,j0,j1; float w00,w01,w10,w11; };

__device__ __forceinline__ Bil make_bil(int py, int px) {
    float cy = ((float)py + 0.5f) * (14.0f/224.0f) - 0.5f;
    float cx = ((float)px + 0.5f) * (14.0f/224.0f) - 0.5f;
    float fy = floorf(cy), fx = floorf(cx);
    float ay = cy - fy,    ax = cx - fx;
    int y0 = (int)fy, x0 = (int)fx;
    Bil b;
    b.i0 = min(13, max(0, y0));   b.i1 = min(13, max(0, y0+1));
    b.j0 = min(13, max(0, x0));   b.j1 = min(13, max(0, x0+1));
    b.w00 = (1.f-ay)*(1.f-ax); b.w01 = (1.f-ay)*ax;
    b.w10 = ay*(1.f-ax);       b.w11 = ay*ax;
    return b;
}

__device__ __forceinline__ float bil_sample(const float* __restrict__ f, int c, const Bil& b) {
    const float* p = f + c*196;
    return b.w00*p[b.i0*14 + b.j0] + b.w01*p[b.i0*14 + b.j1]
         + b.w10*p[b.i1*14 + b.j0] + b.w11*p[b.i1*14 + b.j1];
}

__device__ __forceinline__ uint4 pack8(const float* v) {
    uint4 r;
    __nv_bfloat162 b0 = __float22bfloat162_rn(make_float2(v[0], v[1]));
    __nv_bfloat162 b1 = __float22bfloat162_rn(make_float2(v[2], v[3]));
    __nv_bfloat162 b2 = __float22bfloat162_rn(make_float2(v[4], v[5]));
    __nv_bfloat162 b3 = __float22bfloat162_rn(make_float2(v[6], v[7]));
    r.x = *(uint32_t*)&b0; r.y = *(uint32_t*)&b1;
    r.z = *(uint32_t*)&b2; r.w = *(uint32_t*)&b3;
    return r;
}

// ================= merged prologue: gather + pe + wconv =========================
__global__ void k_prolog(const float* __restrict__ pre_f,
                         const float* __restrict__ first_f,
                         const int* __restrict__ prev,
                         const int* __restrict__ first,
                         const float* __restrict__ ipw, const float* __restrict__ opw,
                         const float* __restrict__ l1w, const float* __restrict__ l2w,
                         const float* __restrict__ oww) {
    __shared__ int sp[N_*2], sf[N_*2];
    __shared__ int skey[256];
    int blk = blockIdx.x;
    int t = threadIdx.x;

    if (blk < 160) {
        int row = blk;
        int b = row / N_, j = row % N_;
        for (int i = t; i < N_*2; i += 256) {
            sp[i] = prev [b*N_*2 + i];
            sf[i] = first[b*N_*2 + i];
        }
        __syncthreads();
        int key = 0x7FFFFFFF;
        if (t < N_) {
            int acc = 0;
            for (int q = 0; q < N_; q++) {
                int qq = (q - t + N_) % N_;
                acc += abs(sp[q*2]   - sf[qq*2]);
                acc += abs(sp[q*2+1] - sf[qq*2+1]);
            }
            key = acc * 128 + t;
        }
        skey[t] = key; __syncthreads();
        for (int s = 128; s >= 1; s >>= 1) {
            if (t < s) skey[t] = min(skey[t], skey[t+s]);
            __syncthreads();
        }
        int best = skey[0] & 127;

        int jj = (j - best + N_) % N_;
        int py = sp[j*2], px = sp[j*2+1];
        Bil bp = make_bil(py, px);
        Bil bf = make_bil(sf[jj*2], sf[jj*2+1]);
        const float* pf = pre_f   + b*C_*196;
        const float* ff = first_f + b*C_*196;
        for (int c = t; c < C_; c += 256) {
            g_preq  [row*C_ + c] = bil_sample(pf, c, bp);
            g_firstq[row*C_ + c] = bil_sample(ff, c, bf);
        }
        if (t < KP - D_) {
            g_q[(size_t)row*KP + D_ + t] = 0.f;
            g_k[(size_t)row*KP + D_ + t] = 0.f;
            g_v[(size_t)row*KP + D_ + t] = 0.f;
        }
        if (t == 0) {
            g_curr[row*2]   = (float)py;
            g_curr[row*2+1] = (float)px;
        }
        return;
    }
    if (blk < 240) {
        int n = blk - 160;
        for (int d = t; d < D_; d += 256) {
            int k2 = d & ~1;
            float div = expf((float)k2 * (-9.210340371976184f / (float)D_));
            float arg = (float)n * div;
            g_pe[n*D_ + d] = (d & 1) ? cosf(arg) : sinf(arg);
        }
        return;
    }

    int b = blk - 240;
    const float* src; __nv_bfloat16* dst;
    int N, K, KC, N64, n;
    if (b < 9280)       { n = b;         src = ipw; dst = g_ipw; N = TD_;  K = D_;   KC = KC_D; N64 = N64_IP; }
    else if (b < 12416) { n = b - 9280;  src = opw; dst = g_opw; N = D_;   K = D_;   KC = KC_D; N64 = N64_OP; }
    else if (b < 14464) { n = b - 12416; src = l1w; dst = g_l1w; N = DFF_; K = D_;   KC = KC_D; N64 = N64_L1; }
    else if (b < 17600) { n = b - 14464; src = l2w; dst = g_l2w; N = D_;   K = DFF_; KC = KC_F; N64 = N64_L2; }
    else                { n = b - 17600; src = oww; dst = g_oww; N = OUTD_;K = D_;   KC = KC_D; N64 = N64_OW; }

    bool nok = n < N;
    const float* srow = src + (size_t)n * K;
    char* dbase = (char*)dst + (size_t)(n >> 6) * CHW;
    uint32_t lrow = (uint32_t)((n & 63) * 128);
    size_t kstride = (size_t)N64 * CHW;
    int units = KC * 8;

    for (int u = t; u < units; u += 256) {
        int k0 = u * 8;
        float v[8];
        if (nok && k0 + 8 <= K) {
            float2 f0 = *(const float2*)(srow + k0);
            float2 f1 = *(const float2*)(srow + k0 + 2);
            float2 f2 = *(const float2*)(srow + k0 + 4);
            float2 f3 = *(const float2*)(srow + k0 + 6);
            v[0]=f0.x; v[1]=f0.y; v[2]=f1.x; v[3]=f1.y;
            v[4]=f2.x; v[5]=f2.y; v[6]=f3.x; v[7]=f3.y;
        } else {
            #pragma unroll
            for (int e = 0; e < 8; e++)
                v[e] = (nok && (k0 + e) < K) ? srow[k0 + e] : 0.f;
        }
        uint32_t loc = lrow + (uint32_t)((k0 & 63) * 2);
        *(uint4*)(dbase + (size_t)(k0 >> 6) * kstride + SW128(loc)) = pack8(v);
    }
}

// ================= tokens = LN(concat) + pe(table) ==============================
__global__ void k_tokens(const float* __restrict__ curr_f,
                         const float* __restrict__ lng,
                         const float* __restrict__ lnb) {
    int row = blockIdx.x;
    int b = row / N_, n = row % N_;
    __shared__ float srow[D_];
    __shared__ float red[256];
    int t = threadIdx.x;

    float cy = g_curr[row*2], cx = g_curr[row*2+1];
    int py = (int)cy, px = (int)cx;
    Bil bb = make_bil(py, px);
    const float* cf = curr_f + b*C_*196;

    float lsum = 0.f;
    for (int d = t; d < D_; d += 256) {
        float v;
        if      (d < C_)        v = g_preq[row*C_ + d];
        else if (d < 2*C_)      v = bil_sample(cf, d - C_, bb);
        else if (d == 2*C_)     v = cy;
        else if (d == 2*C_+1)   v = cx;
        else                    v = g_firstq[row*C_ + (d - (2*C_+2))];
        srow[d] = v;
        lsum += v;
    }
    red[t] = lsum; __syncthreads();
    for (int s = 128; s >= 1; s >>= 1) { if (t < s) red[t] += red[t+s]; __syncthreads(); }
    float mean = red[0] * (1.f/(float)D_);
    __syncthreads();

    float lsq = 0.f;
    for (int d = t; d < D_; d += 256) { float u = srow[d] - mean; lsq += u*u; }
    red[t] = lsq; __syncthreads();
    for (int s = 128; s >= 1; s >>= 1) { if (t < s) red[t] += red[t+s]; __syncthreads(); }
    float rstd = rsqrtf(red[0] * (1.f/(float)D_) + 1e-5f);
    __syncthreads();

    char* cbase = (char*)g_tokc;
    uint32_t lrow = (uint32_t)(row * 128);
    const float* perow = &g_pe[n*D_];
    for (int u = t; u < KP/8; u += 256) {
        int d0 = u * 8;
        float v[8];
        #pragma unroll
        for (int e = 0; e < 8; e++) {
            int d = d0 + e;
            v[e] = (d < D_) ? (lng[d] * ((srow[d] - mean) * rstd) + lnb[d] + perow[d]) : 0.f;
        }
        float4* fp = (float4*)&g_tokens[(size_t)row*KP + d0];
        fp[0] = make_float4(v[0], v[1], v[2], v[3]);
        fp[1] = make_float4(v[4], v[5], v[6], v[7]);
        uint32_t loc = lrow + (uint32_t)((d0 & 63) * 2);
        *(uint4*)(cbase + (size_t)(d0 >> 6) * CHA + SW128(loc)) = pack8(v);
    }
}

// ================= GEMM: 128-wide stages, reg-double-buffered fragments =========
#define NSTG 3
#define STAGE_B (2*CHA + 2*CHW)              // 57344
#define GEMM_SMEM (NSTG*STAGE_B + 64)        // 172096

__global__ __launch_bounds__(256) void k_gemm(
    const __nv_bfloat16* __restrict__ Ac,
    const __nv_bfloat16* __restrict__ Wc,
    int KS, int N64,
    const float* __restrict__ bias,
    float* __restrict__ Part, int ldo, int mode,
    float* __restrict__ oq, float* __restrict__ okk, float* __restrict__ ov)
{
    extern __shared__ char sm[];
    uint32_t smb = smem_u32(sm);
    uint32_t mb = smb + NSTG * STAGE_B;

    int t = threadIdx.x;
    int warp = t >> 5, lane = t & 31;
    int wm = (warp >> 2) * 80;
    int wn = (warp & 3) * 16;
    int qr = lane >> 2, qc2 = (lane & 3) * 2;
    int nb = blockIdx.x, n0 = nb * 64;
    int z = blockIdx.y, S = gridDim.y;
    int ks0 = (KS * z) / S, ks1 = (KS * (z + 1)) / S;
    int nst = ks1 - ks0;

    int sub   = lane & 7;
    int m_off = ((lane >> 3) & 1) * 8 + sub;
    int k_off = (lane >> 4) * 8;
    uint32_t swz = (uint32_t)(sub * 16);
    uint32_t w_row_off = (uint32_t)((wn + m_off) * 128);

    if (t == 0) {
        mbar_init(mb, 1); mbar_init(mb + 8, 1); mbar_init(mb + 16, 1);
        fence_async();
    }
    __syncthreads();

    float acc[5][2][4];
    #pragma unroll
    for (int i = 0; i < 5; i++)
        #pragma unroll
        for (int j = 0; j < 2; j++)
            #pragma unroll
            for (int r = 0; r < 4; r++) acc[i][j][r] = 0.f;

    if (t == 0) {
        #pragma unroll
        for (int p = 0; p < 2; p++) {
            if (p >= nst) break;
            int kg = ks0 + p;
            uint32_t s = p, bar = mb + s*8;
            mbar_expect(bar, STAGE_B);
            bulk_ld(smb + s*STAGE_B, (const char*)Ac + (size_t)(2*kg)*CHA, 2*CHA, bar);
            bulk_ld(smb + s*STAGE_B + 2*CHA,
                    (const char*)Wc + ((size_t)(2*kg)*N64 + nb)*CHW, CHW, bar);
            bulk_ld(smb + s*STAGE_B + 2*CHA + CHW,
                    (const char*)Wc + ((size_t)(2*kg+1)*N64 + nb)*CHW, CHW, bar);
        }
    }

    uint32_t amA[5][4], bmA[4], amB[5][4], bmB[4];

    for (int l = 0; l < nst; l++) {
        int s = l % NSTG;
        mbar_wait(mb + s*8, (uint32_t)((l/NSTG) & 1));
        if (t == 0 && l + 2 < nst) {
            int l2i = l + 2;
            int kg = ks0 + l2i;
            uint32_t s2 = l2i % NSTG, bar = mb + s2*8;
            mbar_expect(bar, STAGE_B);
            bulk_ld(smb + s2*STAGE_B, (const char*)Ac + (size_t)(2*kg)*CHA, 2*CHA, bar);
            bulk_ld(smb + s2*STAGE_B + 2*CHA,
                    (const char*)Wc + ((size_t)(2*kg)*N64 + nb)*CHW, CHW, bar);
            bulk_ld(smb + s2*STAGE_B + 2*CHA + CHW,
                    (const char*)Wc + ((size_t)(2*kg+1)*N64 + nb)*CHW, CHW, bar);
        }
        uint32_t st_b = smb + s*STAGE_B;

        #define LDP(BUFam, BUFbm, p) do { \
            int c2_ = (p) >> 2, kk_ = ((p) & 3) * 16; \
            uint32_t as_ = st_b + (uint32_t)(c2_ * CHA); \
            uint32_t ws_ = st_b + (uint32_t)(2*CHA + c2_ * CHW); \
            uint32_t col_ = ((uint32_t)((kk_ + k_off) * 2)) ^ swz; \
            ldsm4(BUFam[0], as_ + (uint32_t)((wm +   0 + m_off) * 128) + col_); \
            ldsm4(BUFam[1], as_ + (uint32_t)((wm +  16 + m_off) * 128) + col_); \
            ldsm4(BUFam[2], as_ + (uint32_t)((wm +  32 + m_off) * 128) + col_); \
            ldsm4(BUFam[3], as_ + (uint32_t)((wm +  48 + m_off) * 128) + col_); \
            ldsm4(BUFam[4], as_ + (uint32_t)((wm +  64 + m_off) * 128) + col_); \
            ldsm4(BUFbm,    ws_ + w_row_off + col_); \
        } while (0)

        #define MMAP(BUFam, BUFbm) do { \
            _Pragma("unroll") \
            for (int i_ = 0; i_ < 5; i_++) { \
                mma16816(acc[i_][0], BUFam[i_], BUFbm[0], BUFbm[2]); \
                mma16816(acc[i_][1], BUFam[i_], BUFbm[1], BUFbm[3]); \
            } \
        } while (0)

        LDP(amA, bmA, 0);
        #pragma unroll
        for (int p = 0; p < 8; p += 2) {
            if (p + 1 < 8) LDP(amB, bmB, p + 1);
            MMAP(amA, bmA);
            if (p + 2 < 8) LDP(amA, bmA, p + 2);
            MMAP(amB, bmB);
        }
        #undef LDP
        #undef MMAP
        __syncthreads();
    }

    if (mode == 3) {
        float* dst = Part + (size_t)z * M_ * ldo;
        #pragma unroll
        for (int i = 0; i < 5; i++) {
            #pragma unroll
            for (int j = 0; j < 2; j++) {
                int n = n0 + wn + j*8 + qc2;
                #pragma unroll
                for (int h = 0; h < 2; h++) {
                    int m = wm + i*16 + qr + h*8;
                    dst[(size_t)m * ldo + n]     = acc[i][j][h*2 + 0];
                    dst[(size_t)m * ldo + n + 1] = acc[i][j][h*2 + 1];
                }
            }
        }
    } else {  // mode 2: qkv split + bias
        #pragma unroll
        for (int i = 0; i < 5; i++) {
            #pragma unroll
            for (int j = 0; j < 2; j++) {
                int n = n0 + wn + j*8 + qc2;
                #pragma unroll
                for (int h = 0; h < 2; h++) {
                    int m = wm + i*16 + qr + h*8;
                    #pragma unroll
                    for (int c2 = 0; c2 < 2; c2++) {
                        int nn = n + c2;
                        if (nn >= TD_) continue;
                        float v = acc[i][j][h*2 + c2] + __ldg(&bias[nn]);
                        int seg = (nn >= 6148) ? 2 : (nn >= 3074 ? 1 : 0);
                        int col = nn - seg * 3074;
                        float* dstq = (seg == 0) ? oq : (seg == 1 ? okk : ov);
                        dstq[(size_t)m * KP + col] = v;
                    }
                }
            }
        }
    }
}

// ================= scores: S = softmax(QK^T/sqrt(D)) -> g_sc =====================
__global__ __launch_bounds__(256) void k_score() {
    int r = blockIdx.x;
    int b = r / N_;
    int t = threadIdx.x, w = t >> 5, lane = t & 31;
    __shared__ float qs[KP];
    __shared__ float sc[N_];

    float4* qs4 = (float4*)qs;
    const float4* qp = (const float4*)&g_q[(size_t)r*KP];
    for (int u = t; u < KP/4; u += 256) qs4[u] = qp[u];
    __syncthreads();

    float scale = rsqrtf((float)D_);
    // each warp handles pairs (kn, kn+8) -> MLP ~10 float4 loads in flight
    for (int kn = w; kn < N_; kn += 16) {
        const float4* kp0 = (const float4*)&g_k[(size_t)(b*N_ + kn)*KP];
        const float4* kp1 = (const float4*)&g_k[(size_t)(b*N_ + kn + 8)*KP];
        float acc0 = 0.f, acc1 = 0.f;
        #pragma unroll 1
        for (int base = 0; base < KP/4; base += 160) {
            float4 k0v[5], k1v[5];
            int u = base + lane;
            #pragma unroll
            for (int j = 0; j < 5; j++) { k0v[j] = kp0[u + j*32]; k1v[j] = kp1[u + j*32]; }
            #pragma unroll
            for (int j = 0; j < 5; j++) {
                float4 qv = qs4[u + j*32];
                acc0 += qv.x*k0v[j].x + qv.y*k0v[j].y + qv.z*k0v[j].z + qv.w*k0v[j].w;
                acc1 += qv.x*k1v[j].x + qv.y*k1v[j].y + qv.z*k1v[j].z + qv.w*k1v[j].w;
            }
        }
        #pragma unroll
        for (int o = 16; o > 0; o >>= 1) {
            acc0 += __shfl_down_sync(0xffffffffu, acc0, o);
            acc1 += __shfl_down_sync(0xffffffffu, acc1, o);
        }
        if (lane == 0) { sc[kn] = acc0 * scale; sc[kn + 8] = acc1 * scale; }
    }
    __syncthreads();

    if (w == 0) {
        float v0 = (lane      < N_) ? sc[lane]      : -1e30f;
        float v1 = (lane + 32 < N_) ? sc[lane + 32] : -1e30f;
        float v2 = (lane + 64 < N_) ? sc[lane + 64] : -1e30f;
        float mx = fmaxf(v0, fmaxf(v1, v2));
        #pragma unroll
        for (int o = 16; o > 0; o >>= 1) mx = fmaxf(mx, __shfl_xor_sync(0xffffffffu, mx, o));
        float e0 = (lane      < N_) ? expf(v0 - mx) : 0.f;
        float e1 = (lane + 32 < N_) ? expf(v1 - mx) : 0.f;
        float e2 = (lane + 64 < N_) ? expf(v2 - mx) : 0.f;
        float s = e0 + e1 + e2;
        #pragma unroll
        for (int o = 16; o > 0; o >>= 1) s += __shfl_xor_sync(0xffffffffu, s, o);
        float inv = 1.f / s;
        if (lane      < N_) g_sc[r*N_ + lane]      = e0 * inv;
        if (lane + 32 < N_) g_sc[r*N_ + lane + 32] = e1 * inv;
        if (lane + 64 < N_) g_sc[r*N_ + lane + 64] = e2 * inv;
    }
}

// ================= AV: out[q][d] = sum_k sc[q][k] V[k][d]  (smem-staged) ========
// grid (25, 2): blockIdx.x = 128-wide d chunk, blockIdx.y = batch.
#define AV_SMEM (N_*N_*4 + N_*128*4)   // 25600 + 40960 = 66560

__global__ __launch_bounds__(256) void k_av() {
    extern __shared__ float avs[];
    float* ssc = avs;               // [80][80]
    float* sv  = avs + N_*N_;       // [80][128]

    int dc = blockIdx.x;            // 0..24
    int b  = blockIdx.y;
    int t  = threadIdx.x;
    int d0 = dc * 128;

    const float* scb = &g_sc[b*N_*N_];
    for (int i = t; i < N_*N_; i += 256) ssc[i] = scb[i];

    const float* vb = &g_v[(size_t)b*N_*KP + d0];
    for (int i = t; i < N_*32; i += 256) {
        int row = i >> 5, c4 = i & 31;
        ((float4*)sv)[row*32 + c4] = ((const float4*)(vb + (size_t)row*KP))[c4];
    }
    __syncthreads();

    int d  = t & 127;
    int qg = t >> 7;                // 0 or 1 (40 q each)
    float out[40];
    #pragma unroll
    for (int i = 0; i < 40; i++) out[i] = 0.f;

    for (int k0 = 0; k0 < N_; k0 += 8) {
        float vv[8];
        #pragma unroll
        for (int j = 0; j < 8; j++) vv[j] = sv[(k0 + j)*128 + d];
        #pragma unroll 4
        for (int qq = 0; qq < 40; qq++) {
            const float* sq = &ssc[(qg*40 + qq)*N_ + k0];
            float o = out[qq];
            #pragma unroll
            for (int j = 0; j < 8; j++) o += sq[j] * vv[j];
            out[qq] = o;
        }
    }

    // store to chunked+swizzled bf16 g_avc
    char* cbase = (char*)g_avc;
    int dg = d0 + d;
    size_t coff = (size_t)(dg >> 6) * CHA;
    #pragma unroll 4
    for (int qq = 0; qq < 40; qq++) {
        int row = b*N_ + qg*40 + qq;
        uint32_t loc = (uint32_t)(row * 128 + (dg & 63) * 2);
        *(__nv_bfloat16*)(cbase + coff + SW128(loc)) = __float2bfloat16(out[qq]);
    }
}

// ================= layernorm: LN(in0 + Σ partials + pbias) ======================
__global__ void k_ln(const float* __restrict__ in0,
                     const float* __restrict__ part, int partW, int S,
                     const float* __restrict__ pbias,
                     const float* __restrict__ g, const float* __restrict__ bta,
                     float* __restrict__ outF, __nv_bfloat16* __restrict__ outC) {
    int row = blockIdx.x;
    __shared__ float srow[D_];
    __shared__ float red[256];
    int t = threadIdx.x;
    float lsum = 0.f;
    for (int d = t; d < D_; d += 256) {
        float v = in0[(size_t)row*KP + d] + pbias[d];
        for (int z = 0; z < S; z++)
            v += part[((size_t)z*M_ + row)*partW + d];
        srow[d] = v; lsum += v;
    }
    red[t] = lsum; __syncthreads();
    for (int s = 128; s >= 1; s >>= 1) { if (t < s) red[t] += red[t+s]; __syncthreads(); }
    float mean = red[0] * (1.f/(float)D_);
    __syncthreads();
    float lsq = 0.f;
    for (int d = t; d < D_; d += 256) { float u = srow[d] - mean; lsq += u*u; }
    red[t] = lsq; __syncthreads();
    for (int s = 128; s >= 1; s >>= 1) { if (t < s) red[t] += red[t+s]; __syncthreads(); }
    float rstd = rsqrtf(red[0] * (1.f/(float)D_) + 1e-5f);
    __syncthreads();

    char* cbase = (char*)outC;
    uint32_t lrow = (uint32_t)(row * 128);
    for (int u = t; u < KP/8; u += 256) {
        int d0 = u * 8;
        float v[8];
        #pragma unroll
        for (int e = 0; e < 8; e++) {
            int d = d0 + e;
            v[e] = (d < D_) ? (g[d] * ((srow[d] - mean) * rstd) + bta[d]) : 0.f;
        }
        float4* fp = (float4*)&outF[(size_t)row*KP + d0];
        fp[0] = make_float4(v[0], v[1], v[2], v[3]);
        fp[1] = make_float4(v[4], v[5], v[6], v[7]);
        uint32_t loc = lrow + (uint32_t)((d0 & 63) * 2);
        *(uint4*)(cbase + (size_t)(d0 >> 6) * CHA + SW128(loc)) = pack8(v);
    }
}

// ================= h = relu(Σ partials + l1b) -> chunked bf16 ====================
__global__ void k_hred(const float* __restrict__ bias) {
    int row = blockIdx.x;
    int t = threadIdx.x;
    int d0 = t * 8;
    float v[8];
    #pragma unroll
    for (int e = 0; e < 8; e++) v[e] = bias[d0 + e];
    #pragma unroll
    for (int z = 0; z < S_L1; z++) {
        const float4* p = (const float4*)&g_partH[((size_t)z*M_ + row)*PW_L1 + d0];
        float4 a = p[0], b = p[1];
        v[0]+=a.x; v[1]+=a.y; v[2]+=a.z; v[3]+=a.w;
        v[4]+=b.x; v[5]+=b.y; v[6]+=b.z; v[7]+=b.w;
    }
    #pragma unroll
    for (int e = 0; e < 8; e++) v[e] = fmaxf(v[e], 0.f);
    uint32_t loc = (uint32_t)(row * 128 + (d0 & 63) * 2);
    *(uint4*)((char*)g_hc + (size_t)(d0 >> 6) * CHA + SW128(loc)) = pack8(v);
}

// ================= update: o = Σ partials + ob ==================================
__global__ void k_update(const float* __restrict__ ob, float* __restrict__ dout, int iter) {
    int row = blockIdx.x;
    int t = threadIdx.x;
    for (int c = t; c < C_; c += 256) {
        float o = ob[c];
        #pragma unroll
        for (int z = 0; z < S_OW; z++)
            o += g_partO[((size_t)z*M_ + row)*PW_OW + c];
        g_preq[row*C_ + c] += o;
    }
    if (t == 0) {
        float oy = ob[C_], ox = ob[C_ + 1];
        #pragma unroll
        for (int z = 0; z < S_OW; z++) {
            oy += g_partO[((size_t)z*M_ + row)*PW_OW + C_];
            ox += g_partO[((size_t)z*M_ + row)*PW_OW + C_ + 1];
        }
        float ny = fminf(fmaxf(g_curr[row*2]   + oy, 0.f), 223.f);
        float nx = fminf(fmaxf(g_curr[row*2+1] + ox, 0.f), 223.f);
        g_curr[row*2]   = ny;
        g_curr[row*2+1] = nx;
        dout[iter*(B_*N_*2) + row*2]     = ny;
        dout[iter*(B_*N_*2) + row*2 + 1] = nx;
    }
}

// ================= launch =======================================================
extern "C" void kernel_launch(void* const* d_in, const int* in_sizes, int n_in,
                              void* d_out, int out_size) {
    (void)in_sizes; (void)n_in; (void)out_size;
    const float* pre_f   = (const float*)d_in[0];
    const float* curr_f  = (const float*)d_in[1];
    const float* first_f = (const float*)d_in[2];
    const int*   prev_b  = (const int*)  d_in[3];
    const int*   first_b = (const int*)  d_in[4];
    const float* lng = (const float*)d_in[5];
    const float* lnb = (const float*)d_in[6];
    const float* ipw = (const float*)d_in[7];
    const float* ipb = (const float*)d_in[8];
    const float* opw = (const float*)d_in[9];
    const float* opb = (const float*)d_in[10];
    const float* n1g = (const float*)d_in[11];
    const float* n1b = (const float*)d_in[12];
    const float* l1w = (const float*)d_in[13];
    const float* l1b = (const float*)d_in[14];
    const float* l2w = (const float*)d_in[15];
    const float* l2b = (const float*)d_in[16];
    const float* n2g = (const float*)d_in[17];
    const float* n2b = (const float*)d_in[18];
    const float* ow  = (const float*)d_in[19];
    const float* ob  = (const float*)d_in[20];

    cudaFuncSetAttribute(k_gemm, cudaFuncAttributeMaxDynamicSharedMemorySize, GEMM_SMEM);
    cudaFuncSetAttribute(k_av,   cudaFuncAttributeMaxDynamicSharedMemorySize, AV_SMEM);

    __nv_bfloat16 *p_ipw, *p_opw, *p_l1w, *p_l2w, *p_oww;
    cudaGetSymbolAddress((void**)&p_ipw, g_ipw);
    cudaGetSymbolAddress((void**)&p_opw, g_opw);
    cudaGetSymbolAddress((void**)&p_l1w, g_l1w);
    cudaGetSymbolAddress((void**)&p_l2w, g_l2w);
    cudaGetSymbolAddress((void**)&p_oww, g_oww);

    float *p_tokens, *p_q, *p_k, *p_v, *p_x, *p_partD, *p_partH, *p_partO;
    cudaGetSymbolAddress((void**)&p_tokens, g_tokens);
    cudaGetSymbolAddress((void**)&p_q,      g_q);
    cudaGetSymbolAddress((void**)&p_k,      g_k);
    cudaGetSymbolAddress((void**)&p_v,      g_v);
    cudaGetSymbolAddress((void**)&p_x,      g_x);
    cudaGetSymbolAddress((void**)&p_partD,  g_partD);
    cudaGetSymbolAddress((void**)&p_partH,  g_partH);
    cudaGetSymbolAddress((void**)&p_partO,  g_partO);

    __nv_bfloat16 *p_tokc, *p_avc, *p_xc, *p_hc, *p_x2c;
    cudaGetSymbolAddress((void**)&p_tokc, g_tokc);
    cudaGetSymbolAddress((void**)&p_avc,  g_avc);
    cudaGetSymbolAddress((void**)&p_xc,   g_xc);
    cudaGetSymbolAddress((void**)&p_hc,   g_hc);
    cudaGetSymbolAddress((void**)&p_x2c,  g_x2c);

    k_prolog<<<18928, 256>>>(pre_f, first_f, prev_b, first_b,
                             ipw, opw, l1w, l2w, ow);

    dim3 gip(N64_IP, 1);      // 145
    dim3 gop(N64_OP, S_OP);   // 147
    dim3 gl1(N64_L1, S_L1);   // 128
    dim3 gl2(N64_L2, S_L2);   // 147
    dim3 gow(N64_OW, S_OW);   // 136
    dim3 gav(25, 2);          // 50

    for (int it = 0; it < REFINE_; it++) {
        k_tokens<<<M_, 256>>>(curr_f, lng, lnb);
        k_gemm<<<gip, 256, GEMM_SMEM>>>(p_tokc, p_ipw, KS_D, N64_IP, ipb,
                                        nullptr, 0, 2, p_q, p_k, p_v);
        k_score<<<M_, 256>>>();
        k_av<<<gav, 256, AV_SMEM>>>();
        k_gemm<<<gop, 256, GEMM_SMEM>>>(p_avc, p_opw, KS_D, N64_OP, nullptr,
                                        p_partD, PW_D, 3, nullptr, nullptr, nullptr);
        k_ln<<<M_, 256>>>(p_tokens, p_partD, PW_D, S_OP, opb, n1g, n1b, p_x, p_xc);
        k_gemm<<<gl1, 256, GEMM_SMEM>>>(p_xc, p_l1w, KS_D, N64_L1, nullptr,
                                        p_partH, PW_L1, 3, nullptr, nullptr, nullptr);
        k_hred<<<M_, 256>>>(l1b);
        k_gemm<<<gl2, 256, GEMM_SMEM>>>(p_hc, p_l2w, KS_F, N64_L2, nullptr,
                                        p_partD, PW_D, 3, nullptr, nullptr, nullptr);
        k_ln<<<M_, 256>>>(p_x, p_partD, PW_D, S_L2, l2b, n2g, n2b, p_x, p_x2c);
        k_gemm<<<gow, 256, GEMM_SMEM>>>(p_x2c, p_oww, KS_D, N64_OW, nullptr,
                                        p_partO, PW_OW, 3, nullptr, nullptr, nullptr);
        k_update<<<M_, 256>>>(ob, (float*)d_out, it);
    }
}

// round 17
// speedup vs baseline: 1.2878x; 1.1918x over previous
#include <cuda_runtime.h>
#include <cuda_bf16.h>
#include <math.h>
#include <stdint.h>

#define B_    2
#define C_    1024
#define N_    80
#define D_    3074
#define KP    3200      // padded K (50 chunks of 64)
#define TD_   9222
#define DFF_  2048
#define OUTD_ 1026
#define M_    160
#define REFINE_ 3

#define KC_D   50
#define KC_F   32
#define KS_D   25       // 128-wide stages
#define KS_F   16
#define CHA    20480    // A chunk bytes  (160*128)
#define CHW    8192     // W chunk bytes  (64*128)
#define N64_IP 145
#define N64_OP 49
#define N64_L1 32
#define N64_L2 49
#define N64_OW 17

#define S_OP 3
#define S_L1 4
#define S_L2 3
#define S_OW 8
#define PW_D  3136
#define PW_L1 2048
#define PW_OW 1088

#define SC_CH  40       // score d-chunks of 80
#define SC_DW  80
#define SC_PAD 83

// ---------------- chunked+swizzled bf16 weights --------------------------------
__device__ __nv_bfloat16 g_ipw[(size_t)KC_D*N64_IP*4096];
__device__ __nv_bfloat16 g_opw[(size_t)KC_D*N64_OP*4096];
__device__ __nv_bfloat16 g_l1w[(size_t)KC_D*N64_L1*4096];
__device__ __nv_bfloat16 g_l2w[(size_t)KC_F*N64_L2*4096];
__device__ __nv_bfloat16 g_oww[(size_t)KC_D*N64_OW*4096];

// ---------------- chunked+swizzled bf16 activations (GEMM A-side) --------------
__device__ __nv_bfloat16 g_tokc[(size_t)KC_D*10240];
__device__ __nv_bfloat16 g_avc [(size_t)KC_D*10240];
__device__ __nv_bfloat16 g_xc  [(size_t)KC_D*10240];
__device__ __nv_bfloat16 g_hc  [(size_t)KC_F*10240];
__device__ __nv_bfloat16 g_x2c [(size_t)KC_D*10240];

// ---------------- fp32 activations + split-K partials --------------------------
__device__ float g_preq  [M_*C_];
__device__ float g_firstq[M_*C_];
__device__ float g_curr  [M_*2];
__device__ float g_pe    [N_*D_];
__device__ float g_tokens[M_*KP];
__device__ float g_q     [M_*KP];
__device__ float g_k     [M_*KP];
__device__ float g_v     [M_*KP];
__device__ float g_x     [M_*KP];
__device__ float g_sc    [M_*N_];
__device__ float g_scp   [(size_t)SC_CH*B_*N_*N_];
__device__ float g_partD [(size_t)S_OP*M_*PW_D];
__device__ float g_partH [(size_t)S_L1*M_*PW_L1];
__device__ float g_partO [(size_t)S_OW*M_*PW_OW];

// ================= helpers =======================================================
__device__ __forceinline__ uint32_t smem_u32(const void* p) {
    uint32_t a;
    asm("{ .reg .u64 t; cvta.to.shared.u64 t, %1; cvt.u32.u64 %0, t; }" : "=r"(a) : "l"(p));
    return a;
}

#define SW128(bo) ((bo) ^ (((bo) >> 3) & 0x70))

__device__ __forceinline__ void mbar_init(uint32_t mbar, uint32_t cnt) {
    asm volatile("mbarrier.init.shared.b64 [%0], %1;" :: "r"(mbar), "r"(cnt) : "memory");
}
__device__ __forceinline__ void mbar_expect(uint32_t mbar, uint32_t bytes) {
    asm volatile("mbarrier.arrive.expect_tx.shared.b64 _, [%0], %1;"
                 :: "r"(mbar), "r"(bytes) : "memory");
}
__device__ __forceinline__ void mbar_wait(uint32_t mbar, uint32_t parity) {
    asm volatile(
        "{\n\t"
        ".reg .pred P1;\n\t"
        "LAB_%=:\n\t"
        "mbarrier.try_wait.parity.acquire.cta.shared::cta.b64 P1, [%0], %1, 0x989680;\n\t"
        "@P1 bra.uni DONE_%=;\n\t"
        "bra.uni LAB_%=;\n\t"
        "DONE_%=:\n\t"
        "}"
        :: "r"(mbar), "r"(parity) : "memory");
}
__device__ __forceinline__ void fence_async() {
    asm volatile("fence.proxy.async.shared::cta;" ::: "memory");
}
__device__ __forceinline__ void bulk_ld(uint32_t dst, const void* src, uint32_t bytes, uint32_t bar) {
    asm volatile(
        "cp.async.bulk.shared::cluster.global.mbarrier::complete_tx::bytes [%0], [%1], %2, [%3];"
        :: "r"(dst), "l"(src), "r"(bytes), "r"(bar) : "memory");
}
__device__ __forceinline__ void ldsm4(uint32_t* r, uint32_t addr) {
    asm volatile("ldmatrix.sync.aligned.m8n8.x4.shared.b16 {%0,%1,%2,%3}, [%4];"
                 : "=r"(r[0]), "=r"(r[1]), "=r"(r[2]), "=r"(r[3]) : "r"(addr));
}
__device__ __forceinline__ void mma16816(float c[4], const uint32_t a[4],
                                         uint32_t b0, uint32_t b1) {
    asm volatile(
        "mma.sync.aligned.m16n8k16.row.col.f32.bf16.bf16.f32 "
        "{%0,%1,%2,%3},{%4,%5,%6,%7},{%8,%9},{%0,%1,%2,%3};"
        : "+f"(c[0]), "+f"(c[1]), "+f"(c[2]), "+f"(c[3])
        : "r"(a[0]), "r"(a[1]), "r"(a[2]), "r"(a[3]), "r"(b0), "r"(b1));
}

// ================= bilinear sampling ============================================
struct Bil { int i0,i1,j0,j1; float w00,w01,w10,w11; };

__device__ __forceinline__ Bil make_bil(int py, int px) {
    float cy = ((float)py + 0.5f) * (14.0f/224.0f) - 0.5f;
    float cx = ((float)px + 0.5f) * (14.0f/224.0f) - 0.5f;
    float fy = floorf(cy), fx = floorf(cx);
    float ay = cy - fy,    ax = cx - fx;
    int y0 = (int)fy, x0 = (int)fx;
    Bil b;
    b.i0 = min(13, max(0, y0));   b.i1 = min(13, max(0, y0+1));
    b.j0 = min(13, max(0, x0));   b.j1 = min(13, max(0, x0+1));
    b.w00 = (1.f-ay)*(1.f-ax); b.w01 = (1.f-ay)*ax;
    b.w10 = ay*(1.f-ax);       b.w11 = ay*ax;
    return b;
}

__device__ __forceinline__ float bil_sample(const float* __restrict__ f, int c, const Bil& b) {
    const float* p = f + c*196;
    return b.w00*p[b.i0*14 + b.j0] + b.w01*p[b.i0*14 + b.j1]
         + b.w10*p[b.i1*14 + b.j0] + b.w11*p[b.i1*14 + b.j1];
}

__device__ __forceinline__ uint4 pack8(const float* v) {
    uint4 r;
    __nv_bfloat162 b0 = __float22bfloat162_rn(make_float2(v[0], v[1]));
    __nv_bfloat162 b1 = __float22bfloat162_rn(make_float2(v[2], v[3]));
    __nv_bfloat162 b2 = __float22bfloat162_rn(make_float2(v[4], v[5]));
    __nv_bfloat162 b3 = __float22bfloat162_rn(make_float2(v[6], v[7]));
    r.x = *(uint32_t*)&b0; r.y = *(uint32_t*)&b1;
    r.z = *(uint32_t*)&b2; r.w = *(uint32_t*)&b3;
    return r;
}

// ================= merged prologue: gather + pe + wconv =========================
__global__ void k_prolog(const float* __restrict__ pre_f,
                         const float* __restrict__ first_f,
                         const int* __restrict__ prev,
                         const int* __restrict__ first,
                         const float* __restrict__ ipw, const float* __restrict__ opw,
                         const float* __restrict__ l1w, const float* __restrict__ l2w,
                         const float* __restrict__ oww) {
    __shared__ int sp[N_*2], sf[N_*2];
    __shared__ int skey[256];
    int blk = blockIdx.x;
    int t = threadIdx.x;

    if (blk < 160) {
        int row = blk;
        int b = row / N_, j = row % N_;
        for (int i = t; i < N_*2; i += 256) {
            sp[i] = prev [b*N_*2 + i];
            sf[i] = first[b*N_*2 + i];
        }
        __syncthreads();
        int key = 0x7FFFFFFF;
        if (t < N_) {
            int acc = 0;
            for (int q = 0; q < N_; q++) {
                int qq = (q - t + N_) % N_;
                acc += abs(sp[q*2]   - sf[qq*2]);
                acc += abs(sp[q*2+1] - sf[qq*2+1]);
            }
            key = acc * 128 + t;
        }
        skey[t] = key; __syncthreads();
        for (int s = 128; s >= 1; s >>= 1) {
            if (t < s) skey[t] = min(skey[t], skey[t+s]);
            __syncthreads();
        }
        int best = skey[0] & 127;

        int jj = (j - best + N_) % N_;
        int py = sp[j*2], px = sp[j*2+1];
        Bil bp = make_bil(py, px);
        Bil bf = make_bil(sf[jj*2], sf[jj*2+1]);
        const float* pf = pre_f   + b*C_*196;
        const float* ff = first_f + b*C_*196;
        for (int c = t; c < C_; c += 256) {
            g_preq  [row*C_ + c] = bil_sample(pf, c, bp);
            g_firstq[row*C_ + c] = bil_sample(ff, c, bf);
        }
        if (t < KP - D_) {
            g_q[(size_t)row*KP + D_ + t] = 0.f;
            g_k[(size_t)row*KP + D_ + t] = 0.f;
            g_v[(size_t)row*KP + D_ + t] = 0.f;
        }
        if (t == 0) {
            g_curr[row*2]   = (float)py;
            g_curr[row*2+1] = (float)px;
        }
        return;
    }
    if (blk < 240) {
        int n = blk - 160;
        for (int d = t; d < D_; d += 256) {
            int k2 = d & ~1;
            float div = expf((float)k2 * (-9.210340371976184f / (float)D_));
            float arg = (float)n * div;
            g_pe[n*D_ + d] = (d & 1) ? cosf(arg) : sinf(arg);
        }
        return;
    }

    int b = blk - 240;
    const float* src; __nv_bfloat16* dst;
    int N, K, KC, N64, n;
    if (b < 9280)       { n = b;         src = ipw; dst = g_ipw; N = TD_;  K = D_;   KC = KC_D; N64 = N64_IP; }
    else if (b < 12416) { n = b - 9280;  src = opw; dst = g_opw; N = D_;   K = D_;   KC = KC_D; N64 = N64_OP; }
    else if (b < 14464) { n = b - 12416; src = l1w; dst = g_l1w; N = DFF_; K = D_;   KC = KC_D; N64 = N64_L1; }
    else if (b < 17600) { n = b - 14464; src = l2w; dst = g_l2w; N = D_;   K = DFF_; KC = KC_F; N64 = N64_L2; }
    else                { n = b - 17600; src = oww; dst = g_oww; N = OUTD_;K = D_;   KC = KC_D; N64 = N64_OW; }

    bool nok = n < N;
    const float* srow = src + (size_t)n * K;
    char* dbase = (char*)dst + (size_t)(n >> 6) * CHW;
    uint32_t lrow = (uint32_t)((n & 63) * 128);
    size_t kstride = (size_t)N64 * CHW;
    int units = KC * 8;

    for (int u = t; u < units; u += 256) {
        int k0 = u * 8;
        float v[8];
        if (nok && k0 + 8 <= K) {
            float2 f0 = *(const float2*)(srow + k0);
            float2 f1 = *(const float2*)(srow + k0 + 2);
            float2 f2 = *(const float2*)(srow + k0 + 4);
            float2 f3 = *(const float2*)(srow + k0 + 6);
            v[0]=f0.x; v[1]=f0.y; v[2]=f1.x; v[3]=f1.y;
            v[4]=f2.x; v[5]=f2.y; v[6]=f3.x; v[7]=f3.y;
        } else {
            #pragma unroll
            for (int e = 0; e < 8; e++)
                v[e] = (nok && (k0 + e) < K) ? srow[k0 + e] : 0.f;
        }
        uint32_t loc = lrow + (uint32_t)((k0 & 63) * 2);
        *(uint4*)(dbase + (size_t)(k0 >> 6) * kstride + SW128(loc)) = pack8(v);
    }
}

// ================= tokens = LN(concat) + pe(table) ==============================
__global__ void k_tokens(const float* __restrict__ curr_f,
                         const float* __restrict__ lng,
                         const float* __restrict__ lnb) {
    int row = blockIdx.x;
    int b = row / N_, n = row % N_;
    __shared__ float srow[D_];
    __shared__ float red[256];
    int t = threadIdx.x;

    float cy = g_curr[row*2], cx = g_curr[row*2+1];
    int py = (int)cy, px = (int)cx;
    Bil bb = make_bil(py, px);
    const float* cf = curr_f + b*C_*196;

    float lsum = 0.f;
    for (int d = t; d < D_; d += 256) {
        float v;
        if      (d < C_)        v = g_preq[row*C_ + d];
        else if (d < 2*C_)      v = bil_sample(cf, d - C_, bb);
        else if (d == 2*C_)     v = cy;
        else if (d == 2*C_+1)   v = cx;
        else                    v = g_firstq[row*C_ + (d - (2*C_+2))];
        srow[d] = v;
        lsum += v;
    }
    red[t] = lsum; __syncthreads();
    for (int s = 128; s >= 1; s >>= 1) { if (t < s) red[t] += red[t+s]; __syncthreads(); }
    float mean = red[0] * (1.f/(float)D_);
    __syncthreads();

    float lsq = 0.f;
    for (int d = t; d < D_; d += 256) { float u = srow[d] - mean; lsq += u*u; }
    red[t] = lsq; __syncthreads();
    for (int s = 128; s >= 1; s >>= 1) { if (t < s) red[t] += red[t+s]; __syncthreads(); }
    float rstd = rsqrtf(red[0] * (1.f/(float)D_) + 1e-5f);
    __syncthreads();

    char* cbase = (char*)g_tokc;
    uint32_t lrow = (uint32_t)(row * 128);
    const float* perow = &g_pe[n*D_];
    for (int u = t; u < KP/8; u += 256) {
        int d0 = u * 8;
        float v[8];
        #pragma unroll
        for (int e = 0; e < 8; e++) {
            int d = d0 + e;
            v[e] = (d < D_) ? (lng[d] * ((srow[d] - mean) * rstd) + lnb[d] + perow[d]) : 0.f;
        }
        float4* fp = (float4*)&g_tokens[(size_t)row*KP + d0];
        fp[0] = make_float4(v[0], v[1], v[2], v[3]);
        fp[1] = make_float4(v[4], v[5], v[6], v[7]);
        uint32_t loc = lrow + (uint32_t)((d0 & 63) * 2);
        *(uint4*)(cbase + (size_t)(d0 >> 6) * CHA + SW128(loc)) = pack8(v);
    }
}

// ================= GEMM: 128-wide stages, reg-double-buffered fragments =========
#define NSTG 3
#define STAGE_B (2*CHA + 2*CHW)              // 57344
#define GEMM_SMEM (NSTG*STAGE_B + 64)        // 172096

__global__ __launch_bounds__(256) void k_gemm(
    const __nv_bfloat16* __restrict__ Ac,
    const __nv_bfloat16* __restrict__ Wc,
    int KS, int N64,
    const float* __restrict__ bias,
    float* __restrict__ Part, int ldo, int mode,
    float* __restrict__ oq, float* __restrict__ okk, float* __restrict__ ov)
{
    extern __shared__ char sm[];
    uint32_t smb = smem_u32(sm);
    uint32_t mb = smb + NSTG * STAGE_B;

    int t = threadIdx.x;
    int warp = t >> 5, lane = t & 31;
    int wm = (warp >> 2) * 80;
    int wn = (warp & 3) * 16;
    int qr = lane >> 2, qc2 = (lane & 3) * 2;
    int nb = blockIdx.x, n0 = nb * 64;
    int z = blockIdx.y, S = gridDim.y;
    int ks0 = (KS * z) / S, ks1 = (KS * (z + 1)) / S;
    int nst = ks1 - ks0;

    int sub   = lane & 7;
    int m_off = ((lane >> 3) & 1) * 8 + sub;
    int k_off = (lane >> 4) * 8;
    uint32_t swz = (uint32_t)(sub * 16);
    uint32_t w_row_off = (uint32_t)((wn + m_off) * 128);

    if (t == 0) {
        mbar_init(mb, 1); mbar_init(mb + 8, 1); mbar_init(mb + 16, 1);
        fence_async();
    }
    __syncthreads();

    float acc[5][2][4];
    #pragma unroll
    for (int i = 0; i < 5; i++)
        #pragma unroll
        for (int j = 0; j < 2; j++)
            #pragma unroll
            for (int r = 0; r < 4; r++) acc[i][j][r] = 0.f;

    if (t == 0) {
        #pragma unroll
        for (int p = 0; p < 2; p++) {
            if (p >= nst) break;
            int kg = ks0 + p;
            uint32_t s = p, bar = mb + s*8;
            mbar_expect(bar, STAGE_B);
            bulk_ld(smb + s*STAGE_B, (const char*)Ac + (size_t)(2*kg)*CHA, 2*CHA, bar);
            bulk_ld(smb + s*STAGE_B + 2*CHA,
                    (const char*)Wc + ((size_t)(2*kg)*N64 + nb)*CHW, CHW, bar);
            bulk_ld(smb + s*STAGE_B + 2*CHA + CHW,
                    (const char*)Wc + ((size_t)(2*kg+1)*N64 + nb)*CHW, CHW, bar);
        }
    }

    uint32_t amA[5][4], bmA[4], amB[5][4], bmB[4];

    for (int l = 0; l < nst; l++) {
        int s = l % NSTG;
        mbar_wait(mb + s*8, (uint32_t)((l/NSTG) & 1));
        if (t == 0 && l + 2 < nst) {
            int l2i = l + 2;
            int kg = ks0 + l2i;
            uint32_t s2 = l2i % NSTG, bar = mb + s2*8;
            mbar_expect(bar, STAGE_B);
            bulk_ld(smb + s2*STAGE_B, (const char*)Ac + (size_t)(2*kg)*CHA, 2*CHA, bar);
            bulk_ld(smb + s2*STAGE_B + 2*CHA,
                    (const char*)Wc + ((size_t)(2*kg)*N64 + nb)*CHW, CHW, bar);
            bulk_ld(smb + s2*STAGE_B + 2*CHA + CHW,
                    (const char*)Wc + ((size_t)(2*kg+1)*N64 + nb)*CHW, CHW, bar);
        }
        uint32_t st_b = smb + s*STAGE_B;

        #define LDP(BUFam, BUFbm, p) do { \
            int c2_ = (p) >> 2, kk_ = ((p) & 3) * 16; \
            uint32_t as_ = st_b + (uint32_t)(c2_ * CHA); \
            uint32_t ws_ = st_b + (uint32_t)(2*CHA + c2_ * CHW); \
            uint32_t col_ = ((uint32_t)((kk_ + k_off) * 2)) ^ swz; \
            ldsm4(BUFam[0], as_ + (uint32_t)((wm +   0 + m_off) * 128) + col_); \
            ldsm4(BUFam[1], as_ + (uint32_t)((wm +  16 + m_off) * 128) + col_); \
            ldsm4(BUFam[2], as_ + (uint32_t)((wm +  32 + m_off) * 128) + col_); \
            ldsm4(BUFam[3], as_ + (uint32_t)((wm +  48 + m_off) * 128) + col_); \
            ldsm4(BUFam[4], as_ + (uint32_t)((wm +  64 + m_off) * 128) + col_); \
            ldsm4(BUFbm,    ws_ + w_row_off + col_); \
        } while (0)

        #define MMAP(BUFam, BUFbm) do { \
            _Pragma("unroll") \
            for (int i_ = 0; i_ < 5; i_++) { \
                mma16816(acc[i_][0], BUFam[i_], BUFbm[0], BUFbm[2]); \
                mma16816(acc[i_][1], BUFam[i_], BUFbm[1], BUFbm[3]); \
            } \
        } while (0)

        LDP(amA, bmA, 0);
        #pragma unroll
        for (int p = 0; p < 8; p += 2) {
            if (p + 1 < 8) LDP(amB, bmB, p + 1);
            MMAP(amA, bmA);
            if (p + 2 < 8) LDP(amA, bmA, p + 2);
            MMAP(amB, bmB);
        }
        #undef LDP
        #undef MMAP
        __syncthreads();
    }

    if (mode == 3) {
        float* dst = Part + (size_t)z * M_ * ldo;
        #pragma unroll
        for (int i = 0; i < 5; i++) {
            #pragma unroll
            for (int j = 0; j < 2; j++) {
                int n = n0 + wn + j*8 + qc2;
                #pragma unroll
                for (int h = 0; h < 2; h++) {
                    int m = wm + i*16 + qr + h*8;
                    dst[(size_t)m * ldo + n]     = acc[i][j][h*2 + 0];
                    dst[(size_t)m * ldo + n + 1] = acc[i][j][h*2 + 1];
                }
            }
        }
    } else {  // mode 2: qkv split + bias
        #pragma unroll
        for (int i = 0; i < 5; i++) {
            #pragma unroll
            for (int j = 0; j < 2; j++) {
                int n = n0 + wn + j*8 + qc2;
                #pragma unroll
                for (int h = 0; h < 2; h++) {
                    int m = wm + i*16 + qr + h*8;
                    #pragma unroll
                    for (int c2 = 0; c2 < 2; c2++) {
                        int nn = n + c2;
                        if (nn >= TD_) continue;
                        float v = acc[i][j][h*2 + c2] + __ldg(&bias[nn]);
                        int seg = (nn >= 6148) ? 2 : (nn >= 3074 ? 1 : 0);
                        int col = nn - seg * 3074;
                        float* dstq = (seg == 0) ? oq : (seg == 1 ? okk : ov);
                        dstq[(size_t)m * KP + col] = v;
                    }
                }
            }
        }
    }
}

// ================= scores: partial QK^T over 80-wide d chunks ===================
#define SCORE_SMEM (2*N_*SC_PAD*4)   // 53120

__global__ __launch_bounds__(256) void k_score2() {
    extern __shared__ float ss[];
    float* qs = ss;                       // [80][SC_PAD]
    float* ks = ss + N_*SC_PAD;
    int c = blockIdx.x, b = blockIdx.y;
    int t = threadIdx.x;
    int d0 = c * SC_DW;

    for (int i = t; i < N_*SC_DW; i += 256) {
        int r = i / SC_DW, d = i % SC_DW;
        qs[r*SC_PAD + d] = g_q[(size_t)(b*N_ + r)*KP + d0 + d];
        ks[r*SC_PAD + d] = g_k[(size_t)(b*N_ + r)*KP + d0 + d];
    }
    __syncthreads();

    int tq = (t & 15) * 5, tk = (t >> 4) * 5;
    float acc[5][5];
    #pragma unroll
    for (int i = 0; i < 5; i++)
        #pragma unroll
        for (int j = 0; j < 5; j++) acc[i][j] = 0.f;

    #pragma unroll 4
    for (int d = 0; d < SC_DW; d++) {
        float qv[5], kv[5];
        #pragma unroll
        for (int i = 0; i < 5; i++) qv[i] = qs[(tq + i)*SC_PAD + d];
        #pragma unroll
        for (int j = 0; j < 5; j++) kv[j] = ks[(tk + j)*SC_PAD + d];
        #pragma unroll
        for (int i = 0; i < 5; i++)
            #pragma unroll
            for (int j = 0; j < 5; j++)
                acc[i][j] += qv[i] * kv[j];
    }

    float* dst = &g_scp[((size_t)c*B_ + b)*N_*N_];
    #pragma unroll
    for (int i = 0; i < 5; i++)
        #pragma unroll
        for (int j = 0; j < 5; j++)
            dst[(tq + i)*N_ + tk + j] = acc[i][j];
}

// ================= softmax over summed partials ==================================
__global__ __launch_bounds__(128) void k_smax() {
    int r = blockIdx.x;                   // b*80 + q
    int b = r / N_, q = r % N_;
    __shared__ float sc[N_];
    int t = threadIdx.x;
    if (t < N_) {
        float s = 0.f;
        #pragma unroll
        for (int c = 0; c < SC_CH; c++)
            s += g_scp[((size_t)c*B_ + b)*N_*N_ + q*N_ + t];
        sc[t] = s * rsqrtf((float)D_);
    }
    __syncthreads();
    if (t < 32) {
        float v0 = sc[t];
        float v1 = sc[t + 32];
        float v2 = (t + 64 < N_) ? sc[t + 64] : -1e30f;
        float mx = fmaxf(v0, fmaxf(v1, v2));
        #pragma unroll
        for (int o = 16; o > 0; o >>= 1) mx = fmaxf(mx, __shfl_xor_sync(0xffffffffu, mx, o));
        float e0 = expf(v0 - mx);
        float e1 = expf(v1 - mx);
        float e2 = (t + 64 < N_) ? expf(v2 - mx) : 0.f;
        float s = e0 + e1 + e2;
        #pragma unroll
        for (int o = 16; o > 0; o >>= 1) s += __shfl_xor_sync(0xffffffffu, s, o);
        float inv = 1.f / s;
        g_sc[r*N_ + t]      = e0 * inv;
        g_sc[r*N_ + t + 32] = e1 * inv;
        if (t + 64 < N_) g_sc[r*N_ + t + 64] = e2 * inv;
    }
}

// ================= AV: 64-wide d chunks, fully unrolled, V read once ============
#define AV_SMEM (N_*N_*4 + N_*64*4)   // 46080

__global__ __launch_bounds__(256) void k_av() {
    extern __shared__ float avs[];
    float* ssc = avs;               // [80][80]
    float* sv  = avs + N_*N_;       // [80][64]
    int dc = blockIdx.x;            // 0..49
    int b  = blockIdx.y;
    int t  = threadIdx.x;
    int d0 = dc * 64;

    const float* scb = &g_sc[b*N_*N_];
    for (int i = t; i < N_*N_; i += 256) ssc[i] = scb[i];
    const float* vb = &g_v[(size_t)b*N_*KP + d0];
    for (int i = t; i < N_*16; i += 256) {
        int row = i >> 4, c4 = i & 15;
        ((float4*)sv)[row*16 + c4] = ((const float4*)(vb + (size_t)row*KP))[c4];
    }
    __syncthreads();

    int d  = t & 63;
    int qg = (t >> 6) * 20;         // 4 groups of 20 q rows
    float out[20];
    #pragma unroll
    for (int i = 0; i < 20; i++) out[i] = 0.f;

    for (int k = 0; k < N_; k++) {
        float vv = sv[k*64 + d];
        #pragma unroll
        for (int qq = 0; qq < 20; qq++)
            out[qq] += ssc[(qg + qq)*N_ + k] * vv;
    }

    char* cbase = (char*)g_avc;
    size_t coff = (size_t)dc * CHA;
    #pragma unroll
    for (int qq = 0; qq < 20; qq++) {
        int row = b*N_ + qg + qq;
        uint32_t loc = (uint32_t)(row * 128 + d * 2);
        *(__nv_bfloat16*)(cbase + coff + SW128(loc)) = __float2bfloat16(out[qq]);
    }
}

// ================= layernorm: LN(in0 + Σ partials + pbias) ======================
__global__ void k_ln(const float* __restrict__ in0,
                     const float* __restrict__ part, int partW, int S,
                     const float* __restrict__ pbias,
                     const float* __restrict__ g, const float* __restrict__ bta,
                     float* __restrict__ outF, __nv_bfloat16* __restrict__ outC) {
    int row = blockIdx.x;
    __shared__ float srow[D_];
    __shared__ float red[256];
    int t = threadIdx.x;
    float lsum = 0.f;
    for (int d = t; d < D_; d += 256) {
        float v = in0[(size_t)row*KP + d] + pbias[d];
        for (int z = 0; z < S; z++)
            v += part[((size_t)z*M_ + row)*partW + d];
        srow[d] = v; lsum += v;
    }
    red[t] = lsum; __syncthreads();
    for (int s = 128; s >= 1; s >>= 1) { if (t < s) red[t] += red[t+s]; __syncthreads(); }
    float mean = red[0] * (1.f/(float)D_);
    __syncthreads();
    float lsq = 0.f;
    for (int d = t; d < D_; d += 256) { float u = srow[d] - mean; lsq += u*u; }
    red[t] = lsq; __syncthreads();
    for (int s = 128; s >= 1; s >>= 1) { if (t < s) red[t] += red[t+s]; __syncthreads(); }
    float rstd = rsqrtf(red[0] * (1.f/(float)D_) + 1e-5f);
    __syncthreads();

    char* cbase = (char*)outC;
    uint32_t lrow = (uint32_t)(row * 128);
    for (int u = t; u < KP/8; u += 256) {
        int d0 = u * 8;
        float v[8];
        #pragma unroll
        for (int e = 0; e < 8; e++) {
            int d = d0 + e;
            v[e] = (d < D_) ? (g[d] * ((srow[d] - mean) * rstd) + bta[d]) : 0.f;
        }
        float4* fp = (float4*)&outF[(size_t)row*KP + d0];
        fp[0] = make_float4(v[0], v[1], v[2], v[3]);
        fp[1] = make_float4(v[4], v[5], v[6], v[7]);
        uint32_t loc = lrow + (uint32_t)((d0 & 63) * 2);
        *(uint4*)(cbase + (size_t)(d0 >> 6) * CHA + SW128(loc)) = pack8(v);
    }
}

// ================= h = relu(Σ partials + l1b) -> chunked bf16 ====================
__global__ void k_hred(const float* __restrict__ bias) {
    int row = blockIdx.x;
    int t = threadIdx.x;
    int d0 = t * 8;
    float v[8];
    #pragma unroll
    for (int e = 0; e < 8; e++) v[e] = bias[d0 + e];
    #pragma unroll
    for (int z = 0; z < S_L1; z++) {
        const float4* p = (const float4*)&g_partH[((size_t)z*M_ + row)*PW_L1 + d0];
        float4 a = p[0], b = p[1];
        v[0]+=a.x; v[1]+=a.y; v[2]+=a.z; v[3]+=a.w;
        v[4]+=b.x; v[5]+=b.y; v[6]+=b.z; v[7]+=b.w;
    }
    #pragma unroll
    for (int e = 0; e < 8; e++) v[e] = fmaxf(v[e], 0.f);
    uint32_t loc = (uint32_t)(row * 128 + (d0 & 63) * 2);
    *(uint4*)((char*)g_hc + (size_t)(d0 >> 6) * CHA + SW128(loc)) = pack8(v);
}

// ================= update: o = Σ partials + ob ==================================
__global__ void k_update(const float* __restrict__ ob, float* __restrict__ dout, int iter) {
    int row = blockIdx.x;
    int t = threadIdx.x;
    for (int c = t; c < C_; c += 256) {
        float o = ob[c];
        #pragma unroll
        for (int z = 0; z < S_OW; z++)
            o += g_partO[((size_t)z*M_ + row)*PW_OW + c];
        g_preq[row*C_ + c] += o;
    }
    if (t == 0) {
        float oy = ob[C_], ox = ob[C_ + 1];
        #pragma unroll
        for (int z = 0; z < S_OW; z++) {
            oy += g_partO[((size_t)z*M_ + row)*PW_OW + C_];
            ox += g_partO[((size_t)z*M_ + row)*PW_OW + C_ + 1];
        }
        float ny = fminf(fmaxf(g_curr[row*2]   + oy, 0.f), 223.f);
        float nx = fminf(fmaxf(g_curr[row*2+1] + ox, 0.f), 223.f);
        g_curr[row*2]   = ny;
        g_curr[row*2+1] = nx;
        dout[iter*(B_*N_*2) + row*2]     = ny;
        dout[iter*(B_*N_*2) + row*2 + 1] = nx;
    }
}

// ================= launch =======================================================
extern "C" void kernel_launch(void* const* d_in, const int* in_sizes, int n_in,
                              void* d_out, int out_size) {
    (void)in_sizes; (void)n_in; (void)out_size;
    const float* pre_f   = (const float*)d_in[0];
    const float* curr_f  = (const float*)d_in[1];
    const float* first_f = (const float*)d_in[2];
    const int*   prev_b  = (const int*)  d_in[3];
    const int*   first_b = (const int*)  d_in[4];
    const float* lng = (const float*)d_in[5];
    const float* lnb = (const float*)d_in[6];
    const float* ipw = (const float*)d_in[7];
    const float* ipb = (const float*)d_in[8];
    const float* opw = (const float*)d_in[9];
    const float* opb = (const float*)d_in[10];
    const float* n1g = (const float*)d_in[11];
    const float* n1b = (const float*)d_in[12];
    const float* l1w = (const float*)d_in[13];
    const float* l1b = (const float*)d_in[14];
    const float* l2w = (const float*)d_in[15];
    const float* l2b = (const float*)d_in[16];
    const float* n2g = (const float*)d_in[17];
    const float* n2b = (const float*)d_in[18];
    const float* ow  = (const float*)d_in[19];
    const float* ob  = (const float*)d_in[20];

    cudaFuncSetAttribute(k_gemm,   cudaFuncAttributeMaxDynamicSharedMemorySize, GEMM_SMEM);
    cudaFuncSetAttribute(k_score2, cudaFuncAttributeMaxDynamicSharedMemorySize, SCORE_SMEM);
    cudaFuncSetAttribute(k_av,     cudaFuncAttributeMaxDynamicSharedMemorySize, AV_SMEM);

    __nv_bfloat16 *p_ipw, *p_opw, *p_l1w, *p_l2w, *p_oww;
    cudaGetSymbolAddress((void**)&p_ipw, g_ipw);
    cudaGetSymbolAddress((void**)&p_opw, g_opw);
    cudaGetSymbolAddress((void**)&p_l1w, g_l1w);
    cudaGetSymbolAddress((void**)&p_l2w, g_l2w);
    cudaGetSymbolAddress((void**)&p_oww, g_oww);

    float *p_tokens, *p_q, *p_k, *p_v, *p_x, *p_partD, *p_partH, *p_partO;
    cudaGetSymbolAddress((void**)&p_tokens, g_tokens);
    cudaGetSymbolAddress((void**)&p_q,      g_q);
    cudaGetSymbolAddress((void**)&p_k,      g_k);
    cudaGetSymbolAddress((void**)&p_v,      g_v);
    cudaGetSymbolAddress((void**)&p_x,      g_x);
    cudaGetSymbolAddress((void**)&p_partD,  g_partD);
    cudaGetSymbolAddress((void**)&p_partH,  g_partH);
    cudaGetSymbolAddress((void**)&p_partO,  g_partO);

    __nv_bfloat16 *p_tokc, *p_avc, *p_xc, *p_hc, *p_x2c;
    cudaGetSymbolAddress((void**)&p_tokc, g_tokc);
    cudaGetSymbolAddress((void**)&p_avc,  g_avc);
    cudaGetSymbolAddress((void**)&p_xc,   g_xc);
    cudaGetSymbolAddress((void**)&p_hc,   g_hc);
    cudaGetSymbolAddress((void**)&p_x2c,  g_x2c);

    k_prolog<<<18928, 256>>>(pre_f, first_f, prev_b, first_b,
                             ipw, opw, l1w, l2w, ow);

    dim3 gip(N64_IP, 1);      // 145
    dim3 gop(N64_OP, S_OP);   // 147
    dim3 gl1(N64_L1, S_L1);   // 128
    dim3 gl2(N64_L2, S_L2);   // 147
    dim3 gow(N64_OW, S_OW);   // 136
    dim3 gsc(SC_CH, B_);      // 80
    dim3 gav(50, B_);         // 100

    for (int it = 0; it < REFINE_; it++) {
        k_tokens<<<M_, 256>>>(curr_f, lng, lnb);
        k_gemm<<<gip, 256, GEMM_SMEM>>>(p_tokc, p_ipw, KS_D, N64_IP, ipb,
                                        nullptr, 0, 2, p_q, p_k, p_v);
        k_score2<<<gsc, 256, SCORE_SMEM>>>();
        k_smax<<<M_, 128>>>();
        k_av<<<gav, 256, AV_SMEM>>>();
        k_gemm<<<gop, 256, GEMM_SMEM>>>(p_avc, p_opw, KS_D, N64_OP, nullptr,
                                        p_partD, PW_D, 3, nullptr, nullptr, nullptr);
        k_ln<<<M_, 256>>>(p_tokens, p_partD, PW_D, S_OP, opb, n1g, n1b, p_x, p_xc);
        k_gemm<<<gl1, 256, GEMM_SMEM>>>(p_xc, p_l1w, KS_D, N64_L1, nullptr,
                                        p_partH, PW_L1, 3, nullptr, nullptr, nullptr);
        k_hred<<<M_, 256>>>(l1b);
        k_gemm<<<gl2, 256, GEMM_SMEM>>>(p_hc, p_l2w, KS_F, N64_L2, nullptr,
                                        p_partD, PW_D, 3, nullptr, nullptr, nullptr);
        k_ln<<<M_, 256>>>(p_x, p_partD, PW_D, S_L2, l2b, n2g, n2b, p_x, p_x2c);
        k_gemm<<<gow, 256, GEMM_SMEM>>>(p_x2c, p_oww, KS_D, N64_OW, nullptr,
                                        p_partO, PW_OW, 3, nullptr, nullptr, nullptr);
        k_update<<<M_, 256>>>(ob, (float*)d_out, it);
    }
}